// round 7
// baseline (speedup 1.0000x reference)
#include <cuda_runtime.h>
#include <math.h>
#include <stdint.h>

#define NN 50000
#define EE 640000
#define ET 690000   // EE + NN self loops

// ---------------- scratch (device globals) ----------------------------------
__device__ float g_xl1[(size_t)NN * 256];
__device__ float g_xr1[(size_t)NN * 256];
__device__ float g_out1[(size_t)NN * 256];
__device__ float g_xl2[NN * 16];
__device__ float g_xr2[NN * 16];
__device__ int   g_deg[NN];
__device__ int   g_start[NN + 1];
__device__ int   g_cursor[NN];
__device__ int   g_csr_src[ET];

// ---------------- CSR construction ------------------------------------------
__global__ void k_init() {
    int i = blockIdx.x * 256 + threadIdx.x;
    if (i < NN) { g_deg[i] = 1; g_cursor[i] = 0; }   // deg=1: self loop pre-counted
}

__global__ void k_hist(const int* __restrict__ ei) {
    int e = (blockIdx.x * 256 + threadIdx.x) * 4;
    if (e + 4 <= EE) {
        int4 d = *(const int4*)(ei + EE + e);
        atomicAdd(&g_deg[d.x], 1);
        atomicAdd(&g_deg[d.y], 1);
        atomicAdd(&g_deg[d.z], 1);
        atomicAdd(&g_deg[d.w], 1);
    }
}

__global__ void k_scan() {
    __shared__ int sums[1024];
    int t = threadIdx.x;
    const int C = 49;                 // 49*1024 = 50176 >= NN
    int base = t * C;
    int s = 0;
    for (int i = 0; i < C; i++) { int idx = base + i; if (idx < NN) s += g_deg[idx]; }
    sums[t] = s;
    __syncthreads();
    for (int off = 1; off < 1024; off <<= 1) {
        int v = 0;
        if (t >= off) v = sums[t - off];
        __syncthreads();
        sums[t] += v;
        __syncthreads();
    }
    int run = (t == 0) ? 0 : sums[t - 1];
    for (int i = 0; i < C; i++) {
        int idx = base + i;
        if (idx < NN) { g_start[idx] = run; run += g_deg[idx]; }
    }
    if (t == 1023) g_start[NN] = ET;
}

__global__ void k_scatter(const int* __restrict__ ei) {
    int e = blockIdx.x * 256 + threadIdx.x;
    if (e >= ET) return;
    int s = (e < EE) ? ei[e] : e - EE;
    int d = (e < EE) ? ei[EE + e] : e - EE;
    int p = g_start[d] + atomicAdd(&g_cursor[d], 1);
    g_csr_src[p] = s;
}

// ---------------- tf32 helpers ------------------------------------------------
__device__ __forceinline__ float tf32r(float x) {
    uint32_t o;
    asm("cvt.rna.tf32.f32 %0, %1;" : "=r"(o) : "f"(x));
    return __uint_as_float(o);
}

__device__ __forceinline__ void mma_tf32(float c[4], const uint32_t a[4], const uint32_t b[2]) {
    asm volatile(
        "mma.sync.aligned.m16n8k8.row.col.f32.tf32.tf32.f32 "
        "{%0,%1,%2,%3},{%4,%5,%6,%7},{%8,%9},{%0,%1,%2,%3};"
        : "+f"(c[0]), "+f"(c[1]), "+f"(c[2]), "+f"(c[3])
        : "r"(a[0]), "r"(a[1]), "r"(a[2]), "r"(a[3]), "r"(b[0]), "r"(b[1]));
}

// ---------------- GEMM1 (tf32 TC, register double-buffered) ------------------
#define LDA 137
#define LDB 136
__global__ void __launch_bounds__(256) k_gemm1(const float* __restrict__ X,
                                               const float* __restrict__ Wl,
                                               const float* __restrict__ Wr) {
    __shared__ float As[2][32 * LDA];
    __shared__ float Bs[2][32 * LDB];
    const int bm = blockIdx.y * 128;
    const int bn = blockIdx.x * 128;
    const float* Bsrc = (bn < 256) ? Wl : Wr;
    const int bnl = bn & 255;

    const int tid = threadIdx.x;
    const int wid = tid >> 5, lane = tid & 31;
    const int wm = wid >> 2, wn = wid & 3;
    const int g = lane >> 2, tg = lane & 3;

    float acc[4][4][4];
#pragma unroll
    for (int mt = 0; mt < 4; mt++)
#pragma unroll
        for (int nt = 0; nt < 4; nt++)
#pragma unroll
            for (int r = 0; r < 4; r++) acc[mt][nt][r] = 0.f;

    float4 ra[4], rb[4];

    // load slab 0
#pragma unroll
    for (int it = 0; it < 4; it++) {
        int idx = tid + it * 256;
        int m = idx >> 3, kq = (idx & 7) * 4;
        ra[it] = make_float4(0.f, 0.f, 0.f, 0.f);
        if (bm + m < NN) ra[it] = *(const float4*)(X + (size_t)(bm + m) * 128 + kq);
        int k = idx >> 5, nf = (idx & 31) * 4;
        rb[it] = *(const float4*)(Bsrc + (size_t)k * 256 + bnl + nf);
    }
    // store slab 0
#pragma unroll
    for (int it = 0; it < 4; it++) {
        int idx = tid + it * 256;
        int m = idx >> 3, kq = (idx & 7) * 4;
        As[0][(kq + 0) * LDA + m] = tf32r(ra[it].x);
        As[0][(kq + 1) * LDA + m] = tf32r(ra[it].y);
        As[0][(kq + 2) * LDA + m] = tf32r(ra[it].z);
        As[0][(kq + 3) * LDA + m] = tf32r(ra[it].w);
        int k = idx >> 5, nf = (idx & 31) * 4;
        Bs[0][k * LDB + nf + 0] = tf32r(rb[it].x);
        Bs[0][k * LDB + nf + 1] = tf32r(rb[it].y);
        Bs[0][k * LDB + nf + 2] = tf32r(rb[it].z);
        Bs[0][k * LDB + nf + 3] = tf32r(rb[it].w);
    }
    __syncthreads();

#pragma unroll
    for (int i = 0; i < 4; i++) {
        const int cur = i & 1;
        // prefetch next slab into registers (overlaps with MMAs below)
        if (i < 3) {
            int k0 = (i + 1) * 32;
#pragma unroll
            for (int it = 0; it < 4; it++) {
                int idx = tid + it * 256;
                int m = idx >> 3, kq = (idx & 7) * 4;
                ra[it] = make_float4(0.f, 0.f, 0.f, 0.f);
                if (bm + m < NN)
                    ra[it] = *(const float4*)(X + (size_t)(bm + m) * 128 + k0 + kq);
                int k = idx >> 5, nf = (idx & 31) * 4;
                rb[it] = *(const float4*)(Bsrc + (size_t)(k0 + k) * 256 + bnl + nf);
            }
        }
        // MMAs on current buffer
#pragma unroll
        for (int ks = 0; ks < 4; ks++) {
            int kk = ks * 8;
            uint32_t a[4][4], b[4][2];
#pragma unroll
            for (int mt = 0; mt < 4; mt++) {
                int rbase = wm * 64 + mt * 16 + g;
                a[mt][0] = __float_as_uint(As[cur][(kk + tg) * LDA + rbase]);
                a[mt][1] = __float_as_uint(As[cur][(kk + tg) * LDA + rbase + 8]);
                a[mt][2] = __float_as_uint(As[cur][(kk + tg + 4) * LDA + rbase]);
                a[mt][3] = __float_as_uint(As[cur][(kk + tg + 4) * LDA + rbase + 8]);
            }
#pragma unroll
            for (int nt = 0; nt < 4; nt++) {
                int cb = wn * 32 + nt * 8 + g;
                b[nt][0] = __float_as_uint(Bs[cur][(kk + tg) * LDB + cb]);
                b[nt][1] = __float_as_uint(Bs[cur][(kk + tg + 4) * LDB + cb]);
            }
#pragma unroll
            for (int mt = 0; mt < 4; mt++)
#pragma unroll
                for (int nt = 0; nt < 4; nt++)
                    mma_tf32(acc[mt][nt], a[mt], b[nt]);
        }
        // stage next slab
        if (i < 3) {
            const int nxt = (i + 1) & 1;
#pragma unroll
            for (int it = 0; it < 4; it++) {
                int idx = tid + it * 256;
                int m = idx >> 3, kq = (idx & 7) * 4;
                As[nxt][(kq + 0) * LDA + m] = tf32r(ra[it].x);
                As[nxt][(kq + 1) * LDA + m] = tf32r(ra[it].y);
                As[nxt][(kq + 2) * LDA + m] = tf32r(ra[it].z);
                As[nxt][(kq + 3) * LDA + m] = tf32r(ra[it].w);
                int k = idx >> 5, nf = (idx & 31) * 4;
                Bs[nxt][k * LDB + nf + 0] = tf32r(rb[it].x);
                Bs[nxt][k * LDB + nf + 1] = tf32r(rb[it].y);
                Bs[nxt][k * LDB + nf + 2] = tf32r(rb[it].z);
                Bs[nxt][k * LDB + nf + 3] = tf32r(rb[it].w);
            }
            __syncthreads();
        }
    }

    float* dst = (bn < 256) ? g_xl1 : g_xr1;
#pragma unroll
    for (int mt = 0; mt < 4; mt++) {
        int row0 = bm + wm * 64 + mt * 16 + g;
#pragma unroll
        for (int nt = 0; nt < 4; nt++) {
            int col = bnl + wn * 32 + nt * 8 + 2 * tg;
            if (row0 < NN)
                *(float2*)(dst + (size_t)row0 * 256 + col) =
                    make_float2(acc[mt][nt][0], acc[mt][nt][1]);
            if (row0 + 8 < NN)
                *(float2*)(dst + (size_t)(row0 + 8) * 256 + col) =
                    make_float2(acc[mt][nt][2], acc[mt][nt][3]);
        }
    }
}

// ---- layer-1 fused: score + online softmax + aggregate + b1 + ELU -----------
// warp per node; lane = h*4+q owns 8 contiguous floats of head h. Prefetch 1 edge.
__global__ void k_fused1(const float* __restrict__ att1, const float* __restrict__ b1) {
    int t = threadIdx.x;
    int node = blockIdx.x * 8 + (t >> 5);
    if (node >= NN) return;
    int lane = t & 31, h = lane >> 2, q = lane & 3;
    int base = h * 32 + q * 8;
    int p0 = g_start[node], p1 = g_start[node + 1];

    float4 at0 = *(const float4*)(att1 + base);
    float4 at1 = *(const float4*)(att1 + base + 4);
    const float* xrp = g_xr1 + (size_t)node * 256 + base;
    float4 xr0 = *(const float4*)(xrp);
    float4 xr1 = *(const float4*)(xrp + 4);

    float m = -1e30f, den = 0.f;
    float acc[8];
#pragma unroll
    for (int i = 0; i < 8; i++) acc[i] = 0.f;

    // prefetch first edge (deg >= 1 guaranteed by self-loop)
    int sn = g_csr_src[p0];
    const float* xq = g_xl1 + (size_t)sn * 256 + base;
    float4 nl0 = *(const float4*)(xq);
    float4 nl1 = *(const float4*)(xq + 4);

    for (int p = p0; p < p1; p++) {
        float4 l0 = nl0, l1 = nl1;
        if (p + 1 < p1) {
            sn = g_csr_src[p + 1];
            xq = g_xl1 + (size_t)sn * 256 + base;
            nl0 = *(const float4*)(xq);
            nl1 = *(const float4*)(xq + 4);
        }

        float v, sc = 0.f;
        v = l0.x + xr0.x; v = v > 0.f ? v : 0.2f * v; sc += at0.x * v;
        v = l0.y + xr0.y; v = v > 0.f ? v : 0.2f * v; sc += at0.y * v;
        v = l0.z + xr0.z; v = v > 0.f ? v : 0.2f * v; sc += at0.z * v;
        v = l0.w + xr0.w; v = v > 0.f ? v : 0.2f * v; sc += at0.w * v;
        v = l1.x + xr1.x; v = v > 0.f ? v : 0.2f * v; sc += at1.x * v;
        v = l1.y + xr1.y; v = v > 0.f ? v : 0.2f * v; sc += at1.y * v;
        v = l1.z + xr1.z; v = v > 0.f ? v : 0.2f * v; sc += at1.z * v;
        v = l1.w + xr1.w; v = v > 0.f ? v : 0.2f * v; sc += at1.w * v;
        sc += __shfl_xor_sync(0xFFFFFFFFu, sc, 1);
        sc += __shfl_xor_sync(0xFFFFFFFFu, sc, 2);

        if (sc <= m) {
            float w = __expf(sc - m);
            den += w;
            acc[0] += w * l0.x; acc[1] += w * l0.y; acc[2] += w * l0.z; acc[3] += w * l0.w;
            acc[4] += w * l1.x; acc[5] += w * l1.y; acc[6] += w * l1.z; acc[7] += w * l1.w;
        } else {
            float sfac = __expf(m - sc);
            den = den * sfac + 1.f;
            acc[0] = acc[0] * sfac + l0.x; acc[1] = acc[1] * sfac + l0.y;
            acc[2] = acc[2] * sfac + l0.z; acc[3] = acc[3] * sfac + l0.w;
            acc[4] = acc[4] * sfac + l1.x; acc[5] = acc[5] * sfac + l1.y;
            acc[6] = acc[6] * sfac + l1.z; acc[7] = acc[7] * sfac + l1.w;
            m = sc;
        }
    }

    float inv = 1.f / (den + 1e-16f);
    float4 bb0 = *(const float4*)(b1 + base);
    float4 bb1 = *(const float4*)(b1 + base + 4);
    float o[8];
    o[0] = acc[0] * inv + bb0.x; o[1] = acc[1] * inv + bb0.y;
    o[2] = acc[2] * inv + bb0.z; o[3] = acc[3] * inv + bb0.w;
    o[4] = acc[4] * inv + bb1.x; o[5] = acc[5] * inv + bb1.y;
    o[6] = acc[6] * inv + bb1.z; o[7] = acc[7] * inv + bb1.w;
#pragma unroll
    for (int i = 0; i < 8; i++) o[i] = o[i] > 0.f ? o[i] : expm1f(o[i]);
    float* dst = g_out1 + (size_t)node * 256 + base;
    *(float4*)(dst)     = make_float4(o[0], o[1], o[2], o[3]);
    *(float4*)(dst + 4) = make_float4(o[4], o[5], o[6], o[7]);
}

// ---------------- GEMM2: h[NN,256] @ [W2l | W2r][256,32] --------------------
__global__ void k_gemm2(const float* __restrict__ Wl, const float* __restrict__ Wr) {
    __shared__ float ws[256 * 32];
    __shared__ float hs[16][256];
    int tid = threadIdx.x;
    for (int i = tid; i < 256 * 32; i += 256) {
        int k = i >> 5, c = i & 31;
        ws[i] = (c < 16) ? Wl[k * 16 + c] : Wr[k * 16 + c - 16];
    }
    int node0 = blockIdx.x * 16;
    for (int i = tid; i < 16 * 256; i += 256) {
        int m = i >> 8, k = i & 255;
        int node = node0 + m;
        hs[m][k] = (node < NN) ? g_out1[(size_t)node * 256 + k] : 0.f;
    }
    __syncthreads();
    int c = tid & 31;
#pragma unroll
    for (int half = 0; half < 2; half++) {
        int m = (tid >> 5) + half * 8;
        int node = node0 + m;
        if (node < NN) {
            float sacc = 0.f;
#pragma unroll 8
            for (int k = 0; k < 256; k++) sacc += hs[m][k] * ws[k * 32 + c];
            if (c < 16) g_xl2[node * 16 + c] = sacc;
            else        g_xr2[node * 16 + c - 16] = sacc;
        }
    }
}

// ------- layer-2 fused: 2 nodes per warp (16 lanes each), online softmax -----
__global__ void k_fused2(const float* __restrict__ att2, const float* __restrict__ b2,
                         float* __restrict__ dout) {
    int t = threadIdx.x;
    int lane = t & 31;
    int half = lane >> 4, c = lane & 15;
    int node = blockIdx.x * 16 + (t >> 5) * 2 + half;   // NN % 16 == 0 -> always valid
    int p0 = g_start[node], p1 = g_start[node + 1];
    int deg = p1 - p0;
    int dego = __shfl_xor_sync(0xFFFFFFFFu, deg, 16);
    int nit = deg > dego ? deg : dego;

    float xr = g_xr2[node * 16 + c];
    float at = att2[c];
    float m = -1e30f, den = 0.f, acc = 0.f;

    for (int i = 0; i < nit; i++) {
        bool val = i < deg;
        int p = val ? (p0 + i) : p0;
        int s = g_csr_src[p];
        float xl = g_xl2[s * 16 + c];
        float v = xl + xr;
        v = v > 0.f ? v : 0.2f * v;
        float sc = v * at;
        sc += __shfl_xor_sync(0xFFFFFFFFu, sc, 8);
        sc += __shfl_xor_sync(0xFFFFFFFFu, sc, 4);
        sc += __shfl_xor_sync(0xFFFFFFFFu, sc, 2);
        sc += __shfl_xor_sync(0xFFFFFFFFu, sc, 1);
        if (!val) sc = -1e38f;
        if (sc <= m) {
            float w = __expf(sc - m);
            den += w;
            acc += w * xl;
        } else {
            float sfac = __expf(m - sc);
            den = den * sfac + 1.f;
            acc = acc * sfac + xl;
            m = sc;
        }
    }
    float v = acc / (den + 1e-16f) + b2[c];
    dout[node * 16 + c] = v >= 0.f ? v : 0.01f * v;
}

// ---------------- launch ------------------------------------------------------
extern "C" void kernel_launch(void* const* d_in, const int* in_sizes, int n_in,
                              void* d_out, int out_size) {
    const float* x    = (const float*)d_in[0];
    const int*   ei   = (const int*)d_in[1];
    const float* W1l  = (const float*)d_in[2];
    const float* W1r  = (const float*)d_in[3];
    const float* att1 = (const float*)d_in[4];
    const float* b1   = (const float*)d_in[5];
    const float* W2l  = (const float*)d_in[6];
    const float* W2r  = (const float*)d_in[7];
    const float* att2 = (const float*)d_in[8];
    const float* b2   = (const float*)d_in[9];
    float* out = (float*)d_out;

    k_init<<<(NN + 255) / 256, 256>>>();
    k_hist<<<(EE / 4 + 255) / 256, 256>>>(ei);
    k_scan<<<1, 1024>>>();
    k_scatter<<<(ET + 255) / 256, 256>>>(ei);

    dim3 g1(4, (NN + 127) / 128);
    k_gemm1<<<g1, 256>>>(x, W1l, W1r);

    k_fused1<<<(NN + 7) / 8, 256>>>(att1, b1);

    k_gemm2<<<(NN + 15) / 16, 256>>>(W2l, W2r);

    k_fused2<<<NN / 16, 256>>>(att2, b2, out);
}

// round 8
// speedup vs baseline: 1.0306x; 1.0306x over previous
#include <cuda_runtime.h>
#include <math.h>
#include <stdint.h>

#define NN 50000
#define EE 640000
#define ET 690000   // EE + NN self loops

// ---------------- scratch (device globals) ----------------------------------
__device__ float g_xl1[(size_t)NN * 256];
__device__ float g_xr1[(size_t)NN * 256];
__device__ float g_out1[(size_t)NN * 256];
__device__ float g_xl2[NN * 16];
__device__ float g_xr2[NN * 16];
__device__ int   g_deg[NN];
__device__ int   g_start[NN + 1];
__device__ int   g_cursor[NN];
__device__ int   g_csr_src[ET];

// ---------------- CSR construction ------------------------------------------
__global__ void k_init() {
    int i = blockIdx.x * 256 + threadIdx.x;
    if (i < NN) { g_deg[i] = 1; g_cursor[i] = 0; }   // deg=1: self loop pre-counted
}

__global__ void k_hist(const int* __restrict__ ei) {
    int e = (blockIdx.x * 256 + threadIdx.x) * 4;
    if (e + 4 <= EE) {
        int4 d = *(const int4*)(ei + EE + e);
        atomicAdd(&g_deg[d.x], 1);
        atomicAdd(&g_deg[d.y], 1);
        atomicAdd(&g_deg[d.z], 1);
        atomicAdd(&g_deg[d.w], 1);
    }
}

__global__ void k_scan() {
    __shared__ int sums[1024];
    int t = threadIdx.x;
    const int C = 49;                 // 49*1024 = 50176 >= NN
    int base = t * C;
    int s = 0;
    for (int i = 0; i < C; i++) { int idx = base + i; if (idx < NN) s += g_deg[idx]; }
    sums[t] = s;
    __syncthreads();
    for (int off = 1; off < 1024; off <<= 1) {
        int v = 0;
        if (t >= off) v = sums[t - off];
        __syncthreads();
        sums[t] += v;
        __syncthreads();
    }
    int run = (t == 0) ? 0 : sums[t - 1];
    for (int i = 0; i < C; i++) {
        int idx = base + i;
        if (idx < NN) { g_start[idx] = run; run += g_deg[idx]; }
    }
    if (t == 1023) g_start[NN] = ET;
}

__global__ void k_scatter(const int* __restrict__ ei) {
    int e = blockIdx.x * 256 + threadIdx.x;
    if (e >= ET) return;
    int s = (e < EE) ? ei[e] : e - EE;
    int d = (e < EE) ? ei[EE + e] : e - EE;
    int p = g_start[d] + atomicAdd(&g_cursor[d], 1);
    g_csr_src[p] = s;
}

// ---------------- tf32 helpers ------------------------------------------------
__device__ __forceinline__ float tf32r(float x) {
    uint32_t o;
    asm("cvt.rna.tf32.f32 %0, %1;" : "=r"(o) : "f"(x));
    return __uint_as_float(o);
}

__device__ __forceinline__ void mma_tf32(float c[4], const uint32_t a[4], const uint32_t b[2]) {
    asm volatile(
        "mma.sync.aligned.m16n8k8.row.col.f32.tf32.tf32.f32 "
        "{%0,%1,%2,%3},{%4,%5,%6,%7},{%8,%9},{%0,%1,%2,%3};"
        : "+f"(c[0]), "+f"(c[1]), "+f"(c[2]), "+f"(c[3])
        : "r"(a[0]), "r"(a[1]), "r"(a[2]), "r"(a[3]), "r"(b[0]), "r"(b[1]));
}

// ---------------- GEMM1 (tf32 tensor core): X[NN,128] @ [W1l|W1r][128,512] ---
// (round-6 proven version: single-buffer, occupancy 2)
#define LDA 137
#define LDB 136
__global__ void __launch_bounds__(256, 2) k_gemm1(const float* __restrict__ X,
                                                  const float* __restrict__ Wl,
                                                  const float* __restrict__ Wr) {
    __shared__ float As[32 * LDA];
    __shared__ float Bs[32 * LDB];
    const int bm = blockIdx.y * 128;
    const int bn = blockIdx.x * 128;
    const float* Bsrc = (bn < 256) ? Wl : Wr;
    const int bnl = bn & 255;

    const int tid = threadIdx.x;
    const int wid = tid >> 5, lane = tid & 31;
    const int wm = wid >> 2, wn = wid & 3;
    const int g = lane >> 2, tg = lane & 3;

    float acc[4][4][4];
#pragma unroll
    for (int mt = 0; mt < 4; mt++)
#pragma unroll
        for (int nt = 0; nt < 4; nt++)
#pragma unroll
            for (int r = 0; r < 4; r++) acc[mt][nt][r] = 0.f;

    for (int k0 = 0; k0 < 128; k0 += 32) {
#pragma unroll
        for (int it = 0; it < 4; it++) {
            int idx = tid + it * 256;
            int m = idx >> 3, kq = (idx & 7) * 4;
            float4 v = make_float4(0.f, 0.f, 0.f, 0.f);
            int row = bm + m;
            if (row < NN) v = *(const float4*)(X + (size_t)row * 128 + k0 + kq);
            As[(kq + 0) * LDA + m] = tf32r(v.x);
            As[(kq + 1) * LDA + m] = tf32r(v.y);
            As[(kq + 2) * LDA + m] = tf32r(v.z);
            As[(kq + 3) * LDA + m] = tf32r(v.w);
        }
#pragma unroll
        for (int it = 0; it < 4; it++) {
            int idx = tid + it * 256;
            int k = idx >> 5, nf = (idx & 31) * 4;
            float4 v = *(const float4*)(Bsrc + (size_t)(k0 + k) * 256 + bnl + nf);
            Bs[k * LDB + nf + 0] = tf32r(v.x);
            Bs[k * LDB + nf + 1] = tf32r(v.y);
            Bs[k * LDB + nf + 2] = tf32r(v.z);
            Bs[k * LDB + nf + 3] = tf32r(v.w);
        }
        __syncthreads();

#pragma unroll
        for (int ks = 0; ks < 4; ks++) {
            int kk = ks * 8;
            uint32_t a[4][4], b[4][2];
#pragma unroll
            for (int mt = 0; mt < 4; mt++) {
                int rb = wm * 64 + mt * 16 + g;
                a[mt][0] = __float_as_uint(As[(kk + tg) * LDA + rb]);
                a[mt][1] = __float_as_uint(As[(kk + tg) * LDA + rb + 8]);
                a[mt][2] = __float_as_uint(As[(kk + tg + 4) * LDA + rb]);
                a[mt][3] = __float_as_uint(As[(kk + tg + 4) * LDA + rb + 8]);
            }
#pragma unroll
            for (int nt = 0; nt < 4; nt++) {
                int cb = wn * 32 + nt * 8 + g;
                b[nt][0] = __float_as_uint(Bs[(kk + tg) * LDB + cb]);
                b[nt][1] = __float_as_uint(Bs[(kk + tg + 4) * LDB + cb]);
            }
#pragma unroll
            for (int mt = 0; mt < 4; mt++)
#pragma unroll
                for (int nt = 0; nt < 4; nt++)
                    mma_tf32(acc[mt][nt], a[mt], b[nt]);
        }
        __syncthreads();
    }

    float* dst = (bn < 256) ? g_xl1 : g_xr1;
#pragma unroll
    for (int mt = 0; mt < 4; mt++) {
        int row0 = bm + wm * 64 + mt * 16 + g;
#pragma unroll
        for (int nt = 0; nt < 4; nt++) {
            int col = bnl + wn * 32 + nt * 8 + 2 * tg;
            if (row0 < NN)
                *(float2*)(dst + (size_t)row0 * 256 + col) =
                    make_float2(acc[mt][nt][0], acc[mt][nt][1]);
            if (row0 + 8 < NN)
                *(float2*)(dst + (size_t)(row0 + 8) * 256 + col) =
                    make_float2(acc[mt][nt][2], acc[mt][nt][3]);
        }
    }
}

// ---- layer-1 fused: score + online softmax + aggregate + b1 + ELU -----------
// (round-6 proven version: warp per node, lane = h*4+q, no explicit prefetch)
__global__ void k_fused1(const float* __restrict__ att1, const float* __restrict__ b1) {
    int t = threadIdx.x;
    int node = blockIdx.x * 8 + (t >> 5);
    if (node >= NN) return;
    int lane = t & 31, h = lane >> 2, q = lane & 3;
    int base = h * 32 + q * 8;
    int p0 = g_start[node], p1 = g_start[node + 1];

    float4 at0 = *(const float4*)(att1 + base);
    float4 at1 = *(const float4*)(att1 + base + 4);
    const float* xrp = g_xr1 + (size_t)node * 256 + base;
    float4 xr0 = *(const float4*)(xrp);
    float4 xr1 = *(const float4*)(xrp + 4);

    float m = -1e30f, den = 0.f;
    float acc[8];
#pragma unroll
    for (int i = 0; i < 8; i++) acc[i] = 0.f;

    for (int p = p0; p < p1; p++) {
        int s = g_csr_src[p];
        const float* xlp = g_xl1 + (size_t)s * 256 + base;
        float4 l0 = *(const float4*)(xlp);
        float4 l1 = *(const float4*)(xlp + 4);

        float v, sc = 0.f;
        v = l0.x + xr0.x; v = v > 0.f ? v : 0.2f * v; sc += at0.x * v;
        v = l0.y + xr0.y; v = v > 0.f ? v : 0.2f * v; sc += at0.y * v;
        v = l0.z + xr0.z; v = v > 0.f ? v : 0.2f * v; sc += at0.z * v;
        v = l0.w + xr0.w; v = v > 0.f ? v : 0.2f * v; sc += at0.w * v;
        v = l1.x + xr1.x; v = v > 0.f ? v : 0.2f * v; sc += at1.x * v;
        v = l1.y + xr1.y; v = v > 0.f ? v : 0.2f * v; sc += at1.y * v;
        v = l1.z + xr1.z; v = v > 0.f ? v : 0.2f * v; sc += at1.z * v;
        v = l1.w + xr1.w; v = v > 0.f ? v : 0.2f * v; sc += at1.w * v;
        sc += __shfl_xor_sync(0xFFFFFFFFu, sc, 1);
        sc += __shfl_xor_sync(0xFFFFFFFFu, sc, 2);

        if (sc <= m) {
            float w = __expf(sc - m);
            den += w;
            acc[0] += w * l0.x; acc[1] += w * l0.y; acc[2] += w * l0.z; acc[3] += w * l0.w;
            acc[4] += w * l1.x; acc[5] += w * l1.y; acc[6] += w * l1.z; acc[7] += w * l1.w;
        } else {
            float sfac = __expf(m - sc);
            den = den * sfac + 1.f;
            acc[0] = acc[0] * sfac + l0.x; acc[1] = acc[1] * sfac + l0.y;
            acc[2] = acc[2] * sfac + l0.z; acc[3] = acc[3] * sfac + l0.w;
            acc[4] = acc[4] * sfac + l1.x; acc[5] = acc[5] * sfac + l1.y;
            acc[6] = acc[6] * sfac + l1.z; acc[7] = acc[7] * sfac + l1.w;
            m = sc;
        }
    }

    float inv = 1.f / (den + 1e-16f);
    float4 bb0 = *(const float4*)(b1 + base);
    float4 bb1 = *(const float4*)(b1 + base + 4);
    float o[8];
    o[0] = acc[0] * inv + bb0.x; o[1] = acc[1] * inv + bb0.y;
    o[2] = acc[2] * inv + bb0.z; o[3] = acc[3] * inv + bb0.w;
    o[4] = acc[4] * inv + bb1.x; o[5] = acc[5] * inv + bb1.y;
    o[6] = acc[6] * inv + bb1.z; o[7] = acc[7] * inv + bb1.w;
#pragma unroll
    for (int i = 0; i < 8; i++) o[i] = o[i] > 0.f ? o[i] : expm1f(o[i]);
    float* dst = g_out1 + (size_t)node * 256 + base;
    *(float4*)(dst)     = make_float4(o[0], o[1], o[2], o[3]);
    *(float4*)(dst + 4) = make_float4(o[4], o[5], o[6], o[7]);
}

// ---------------- GEMM2: h[NN,256] @ [W2l | W2r][256,32] --------------------
__global__ void k_gemm2(const float* __restrict__ Wl, const float* __restrict__ Wr) {
    __shared__ float ws[256 * 32];
    __shared__ float hs[16][256];
    int tid = threadIdx.x;
    for (int i = tid; i < 256 * 32; i += 256) {
        int k = i >> 5, c = i & 31;
        ws[i] = (c < 16) ? Wl[k * 16 + c] : Wr[k * 16 + c - 16];
    }
    int node0 = blockIdx.x * 16;
    for (int i = tid; i < 16 * 256; i += 256) {
        int m = i >> 8, k = i & 255;
        int node = node0 + m;
        hs[m][k] = (node < NN) ? g_out1[(size_t)node * 256 + k] : 0.f;
    }
    __syncthreads();
    int c = tid & 31;
#pragma unroll
    for (int half = 0; half < 2; half++) {
        int m = (tid >> 5) + half * 8;
        int node = node0 + m;
        if (node < NN) {
            float sacc = 0.f;
#pragma unroll 8
            for (int k = 0; k < 256; k++) sacc += hs[m][k] * ws[k * 32 + c];
            if (c < 16) g_xl2[node * 16 + c] = sacc;
            else        g_xr2[node * 16 + c - 16] = sacc;
        }
    }
}

// ------- layer-2 fused: 2 nodes per warp (16 lanes each), online softmax -----
__global__ void k_fused2(const float* __restrict__ att2, const float* __restrict__ b2,
                         float* __restrict__ dout) {
    int t = threadIdx.x;
    int lane = t & 31;
    int half = lane >> 4, c = lane & 15;
    int node = blockIdx.x * 16 + (t >> 5) * 2 + half;   // NN % 16 == 0 -> always valid
    int p0 = g_start[node], p1 = g_start[node + 1];
    int deg = p1 - p0;
    int dego = __shfl_xor_sync(0xFFFFFFFFu, deg, 16);
    int nit = deg > dego ? deg : dego;

    float xr = g_xr2[node * 16 + c];
    float at = att2[c];
    float m = -1e30f, den = 0.f, acc = 0.f;

    for (int i = 0; i < nit; i++) {
        bool val = i < deg;
        int p = val ? (p0 + i) : p0;
        int s = g_csr_src[p];
        float xl = g_xl2[s * 16 + c];
        float v = xl + xr;
        v = v > 0.f ? v : 0.2f * v;
        float sc = v * at;
        sc += __shfl_xor_sync(0xFFFFFFFFu, sc, 8);
        sc += __shfl_xor_sync(0xFFFFFFFFu, sc, 4);
        sc += __shfl_xor_sync(0xFFFFFFFFu, sc, 2);
        sc += __shfl_xor_sync(0xFFFFFFFFu, sc, 1);
        if (!val) sc = -1e38f;
        if (sc <= m) {
            float w = __expf(sc - m);
            den += w;
            acc += w * xl;
        } else {
            float sfac = __expf(m - sc);
            den = den * sfac + 1.f;
            acc = acc * sfac + xl;
            m = sc;
        }
    }
    float v = acc / (den + 1e-16f) + b2[c];
    dout[node * 16 + c] = v >= 0.f ? v : 0.01f * v;
}

// ---------------- launch ------------------------------------------------------
extern "C" void kernel_launch(void* const* d_in, const int* in_sizes, int n_in,
                              void* d_out, int out_size) {
    const float* x    = (const float*)d_in[0];
    const int*   ei   = (const int*)d_in[1];
    const float* W1l  = (const float*)d_in[2];
    const float* W1r  = (const float*)d_in[3];
    const float* att1 = (const float*)d_in[4];
    const float* b1   = (const float*)d_in[5];
    const float* W2l  = (const float*)d_in[6];
    const float* W2r  = (const float*)d_in[7];
    const float* att2 = (const float*)d_in[8];
    const float* b2   = (const float*)d_in[9];
    float* out = (float*)d_out;

    k_init<<<(NN + 255) / 256, 256>>>();
    k_hist<<<(EE / 4 + 255) / 256, 256>>>(ei);
    k_scan<<<1, 1024>>>();
    k_scatter<<<(ET + 255) / 256, 256>>>(ei);

    dim3 g1(4, (NN + 127) / 128);
    k_gemm1<<<g1, 256>>>(x, W1l, W1r);

    k_fused1<<<(NN + 7) / 8, 256>>>(att1, b1);

    k_gemm2<<<(NN + 15) / 16, 256>>>(W2l, W2r);

    k_fused2<<<NN / 16, 256>>>(att2, b2, out);
}

// round 9
// speedup vs baseline: 1.0670x; 1.0353x over previous
#include <cuda_runtime.h>
#include <cuda_fp16.h>
#include <math.h>
#include <stdint.h>

#define NN 50000
#define EE 640000
#define ET 690000   // EE + NN self loops

// ---------------- scratch (device globals) ----------------------------------
__device__ __half g_xl1h[(size_t)NN * 256];
__device__ __half g_xr1h[(size_t)NN * 256];
__device__ float  g_out1[(size_t)NN * 256];
__device__ float  g_xl2[NN * 16];
__device__ float  g_xr2[NN * 16];
__device__ int    g_deg[NN];
__device__ int    g_start[NN + 1];
__device__ int    g_cursor[NN];
__device__ int    g_csr_src[ET];

// ---------------- CSR construction ------------------------------------------
__global__ void k_init() {
    int i = blockIdx.x * 256 + threadIdx.x;
    if (i < NN) { g_deg[i] = 1; g_cursor[i] = 0; }   // deg=1: self loop pre-counted
}

__global__ void k_hist(const int* __restrict__ ei) {
    int e = (blockIdx.x * 256 + threadIdx.x) * 4;
    if (e + 4 <= EE) {
        int4 d = *(const int4*)(ei + EE + e);
        atomicAdd(&g_deg[d.x], 1);
        atomicAdd(&g_deg[d.y], 1);
        atomicAdd(&g_deg[d.z], 1);
        atomicAdd(&g_deg[d.w], 1);
    }
}

__global__ void k_scan() {
    __shared__ int sums[1024];
    int t = threadIdx.x;
    const int C = 49;                 // 49*1024 = 50176 >= NN
    int base = t * C;
    int s = 0;
    for (int i = 0; i < C; i++) { int idx = base + i; if (idx < NN) s += g_deg[idx]; }
    sums[t] = s;
    __syncthreads();
    for (int off = 1; off < 1024; off <<= 1) {
        int v = 0;
        if (t >= off) v = sums[t - off];
        __syncthreads();
        sums[t] += v;
        __syncthreads();
    }
    int run = (t == 0) ? 0 : sums[t - 1];
    for (int i = 0; i < C; i++) {
        int idx = base + i;
        if (idx < NN) { g_start[idx] = run; run += g_deg[idx]; }
    }
    if (t == 1023) g_start[NN] = ET;
}

__global__ void k_scatter(const int* __restrict__ ei) {
    int e = blockIdx.x * 256 + threadIdx.x;
    if (e >= ET) return;
    int s = (e < EE) ? ei[e] : e - EE;
    int d = (e < EE) ? ei[EE + e] : e - EE;
    int p = g_start[d] + atomicAdd(&g_cursor[d], 1);
    g_csr_src[p] = s;
}

// ---------------- tf32 helpers ------------------------------------------------
__device__ __forceinline__ float tf32r(float x) {
    uint32_t o;
    asm("cvt.rna.tf32.f32 %0, %1;" : "=r"(o) : "f"(x));
    return __uint_as_float(o);
}

__device__ __forceinline__ void mma_tf32(float c[4], const uint32_t a[4], const uint32_t b[2]) {
    asm volatile(
        "mma.sync.aligned.m16n8k8.row.col.f32.tf32.tf32.f32 "
        "{%0,%1,%2,%3},{%4,%5,%6,%7},{%8,%9},{%0,%1,%2,%3};"
        : "+f"(c[0]), "+f"(c[1]), "+f"(c[2]), "+f"(c[3])
        : "r"(a[0]), "r"(a[1]), "r"(a[2]), "r"(a[3]), "r"(b[0]), "r"(b[1]));
}

// ---------------- GEMM1 (tf32 tensor core): X[NN,128] @ [W1l|W1r][128,512] ---
// output stored as fp16
#define LDA 137
#define LDB 136
__global__ void __launch_bounds__(256, 2) k_gemm1(const float* __restrict__ X,
                                                  const float* __restrict__ Wl,
                                                  const float* __restrict__ Wr) {
    __shared__ float As[32 * LDA];
    __shared__ float Bs[32 * LDB];
    const int bm = blockIdx.y * 128;
    const int bn = blockIdx.x * 128;
    const float* Bsrc = (bn < 256) ? Wl : Wr;
    const int bnl = bn & 255;

    const int tid = threadIdx.x;
    const int wid = tid >> 5, lane = tid & 31;
    const int wm = wid >> 2, wn = wid & 3;
    const int g = lane >> 2, tg = lane & 3;

    float acc[4][4][4];
#pragma unroll
    for (int mt = 0; mt < 4; mt++)
#pragma unroll
        for (int nt = 0; nt < 4; nt++)
#pragma unroll
            for (int r = 0; r < 4; r++) acc[mt][nt][r] = 0.f;

    for (int k0 = 0; k0 < 128; k0 += 32) {
#pragma unroll
        for (int it = 0; it < 4; it++) {
            int idx = tid + it * 256;
            int m = idx >> 3, kq = (idx & 7) * 4;
            float4 v = make_float4(0.f, 0.f, 0.f, 0.f);
            int row = bm + m;
            if (row < NN) v = *(const float4*)(X + (size_t)row * 128 + k0 + kq);
            As[(kq + 0) * LDA + m] = tf32r(v.x);
            As[(kq + 1) * LDA + m] = tf32r(v.y);
            As[(kq + 2) * LDA + m] = tf32r(v.z);
            As[(kq + 3) * LDA + m] = tf32r(v.w);
        }
#pragma unroll
        for (int it = 0; it < 4; it++) {
            int idx = tid + it * 256;
            int k = idx >> 5, nf = (idx & 31) * 4;
            float4 v = *(const float4*)(Bsrc + (size_t)(k0 + k) * 256 + bnl + nf);
            Bs[k * LDB + nf + 0] = tf32r(v.x);
            Bs[k * LDB + nf + 1] = tf32r(v.y);
            Bs[k * LDB + nf + 2] = tf32r(v.z);
            Bs[k * LDB + nf + 3] = tf32r(v.w);
        }
        __syncthreads();

#pragma unroll
        for (int ks = 0; ks < 4; ks++) {
            int kk = ks * 8;
            uint32_t a[4][4], b[4][2];
#pragma unroll
            for (int mt = 0; mt < 4; mt++) {
                int rb = wm * 64 + mt * 16 + g;
                a[mt][0] = __float_as_uint(As[(kk + tg) * LDA + rb]);
                a[mt][1] = __float_as_uint(As[(kk + tg) * LDA + rb + 8]);
                a[mt][2] = __float_as_uint(As[(kk + tg + 4) * LDA + rb]);
                a[mt][3] = __float_as_uint(As[(kk + tg + 4) * LDA + rb + 8]);
            }
#pragma unroll
            for (int nt = 0; nt < 4; nt++) {
                int cb = wn * 32 + nt * 8 + g;
                b[nt][0] = __float_as_uint(Bs[(kk + tg) * LDB + cb]);
                b[nt][1] = __float_as_uint(Bs[(kk + tg + 4) * LDB + cb]);
            }
#pragma unroll
            for (int mt = 0; mt < 4; mt++)
#pragma unroll
                for (int nt = 0; nt < 4; nt++)
                    mma_tf32(acc[mt][nt], a[mt], b[nt]);
        }
        __syncthreads();
    }

    __half2* dst = (__half2*)((bn < 256) ? g_xl1h : g_xr1h);
#pragma unroll
    for (int mt = 0; mt < 4; mt++) {
        int row0 = bm + wm * 64 + mt * 16 + g;
#pragma unroll
        for (int nt = 0; nt < 4; nt++) {
            int col = bnl + wn * 32 + nt * 8 + 2 * tg;   // even
            if (row0 < NN)
                dst[((size_t)row0 * 256 + col) >> 1] =
                    __floats2half2_rn(acc[mt][nt][0], acc[mt][nt][1]);
            if (row0 + 8 < NN)
                dst[((size_t)(row0 + 8) * 256 + col) >> 1] =
                    __floats2half2_rn(acc[mt][nt][2], acc[mt][nt][3]);
        }
    }
}

// ---- layer-1 fused: score + online softmax + aggregate + b1 + ELU -----------
// warp per node; lane = h*4+q owns 8 contiguous (fp16) floats of head h.
__global__ void k_fused1(const float* __restrict__ att1, const float* __restrict__ b1) {
    int t = threadIdx.x;
    int node = blockIdx.x * 8 + (t >> 5);
    if (node >= NN) return;
    int lane = t & 31, h = lane >> 2, q = lane & 3;
    int base = h * 32 + q * 8;
    int p0 = g_start[node], p1 = g_start[node + 1];

    float4 at0 = *(const float4*)(att1 + base);
    float4 at1 = *(const float4*)(att1 + base + 4);

    // xr: 8 fp16 -> fp32
    uint4 rr = *(const uint4*)(g_xr1h + (size_t)node * 256 + base);
    float2 xrA = __half22float2(*(__half2*)&rr.x);
    float2 xrB = __half22float2(*(__half2*)&rr.y);
    float2 xrC = __half22float2(*(__half2*)&rr.z);
    float2 xrD = __half22float2(*(__half2*)&rr.w);

    float m = -1e30f, den = 0.f;
    float acc[8];
#pragma unroll
    for (int i = 0; i < 8; i++) acc[i] = 0.f;

    for (int p = p0; p < p1; p++) {
        int s = g_csr_src[p];
        uint4 raw = *(const uint4*)(g_xl1h + (size_t)s * 256 + base);
        float2 lA = __half22float2(*(__half2*)&raw.x);
        float2 lB = __half22float2(*(__half2*)&raw.y);
        float2 lC = __half22float2(*(__half2*)&raw.z);
        float2 lD = __half22float2(*(__half2*)&raw.w);

        float v, sc = 0.f;
        v = lA.x + xrA.x; v = v > 0.f ? v : 0.2f * v; sc += at0.x * v;
        v = lA.y + xrA.y; v = v > 0.f ? v : 0.2f * v; sc += at0.y * v;
        v = lB.x + xrB.x; v = v > 0.f ? v : 0.2f * v; sc += at0.z * v;
        v = lB.y + xrB.y; v = v > 0.f ? v : 0.2f * v; sc += at0.w * v;
        v = lC.x + xrC.x; v = v > 0.f ? v : 0.2f * v; sc += at1.x * v;
        v = lC.y + xrC.y; v = v > 0.f ? v : 0.2f * v; sc += at1.y * v;
        v = lD.x + xrD.x; v = v > 0.f ? v : 0.2f * v; sc += at1.z * v;
        v = lD.y + xrD.y; v = v > 0.f ? v : 0.2f * v; sc += at1.w * v;
        sc += __shfl_xor_sync(0xFFFFFFFFu, sc, 1);
        sc += __shfl_xor_sync(0xFFFFFFFFu, sc, 2);

        if (sc <= m) {
            float w = __expf(sc - m);
            den += w;
            acc[0] += w * lA.x; acc[1] += w * lA.y; acc[2] += w * lB.x; acc[3] += w * lB.y;
            acc[4] += w * lC.x; acc[5] += w * lC.y; acc[6] += w * lD.x; acc[7] += w * lD.y;
        } else {
            float sfac = __expf(m - sc);
            den = den * sfac + 1.f;
            acc[0] = acc[0] * sfac + lA.x; acc[1] = acc[1] * sfac + lA.y;
            acc[2] = acc[2] * sfac + lB.x; acc[3] = acc[3] * sfac + lB.y;
            acc[4] = acc[4] * sfac + lC.x; acc[5] = acc[5] * sfac + lC.y;
            acc[6] = acc[6] * sfac + lD.x; acc[7] = acc[7] * sfac + lD.y;
            m = sc;
        }
    }

    float inv = 1.f / (den + 1e-16f);
    float4 bb0 = *(const float4*)(b1 + base);
    float4 bb1 = *(const float4*)(b1 + base + 4);
    float o[8];
    o[0] = acc[0] * inv + bb0.x; o[1] = acc[1] * inv + bb0.y;
    o[2] = acc[2] * inv + bb0.z; o[3] = acc[3] * inv + bb0.w;
    o[4] = acc[4] * inv + bb1.x; o[5] = acc[5] * inv + bb1.y;
    o[6] = acc[6] * inv + bb1.z; o[7] = acc[7] * inv + bb1.w;
#pragma unroll
    for (int i = 0; i < 8; i++) o[i] = o[i] > 0.f ? o[i] : expm1f(o[i]);
    float* dst = g_out1 + (size_t)node * 256 + base;
    *(float4*)(dst)     = make_float4(o[0], o[1], o[2], o[3]);
    *(float4*)(dst + 4) = make_float4(o[4], o[5], o[6], o[7]);
}

// ---------------- GEMM2: h[NN,256] @ [W2l | W2r][256,32] --------------------
__global__ void k_gemm2(const float* __restrict__ Wl, const float* __restrict__ Wr) {
    __shared__ float ws[256 * 32];
    __shared__ float hs[16][256];
    int tid = threadIdx.x;
    for (int i = tid; i < 256 * 32; i += 256) {
        int k = i >> 5, c = i & 31;
        ws[i] = (c < 16) ? Wl[k * 16 + c] : Wr[k * 16 + c - 16];
    }
    int node0 = blockIdx.x * 16;
    for (int i = tid; i < 16 * 256; i += 256) {
        int m = i >> 8, k = i & 255;
        int node = node0 + m;
        hs[m][k] = (node < NN) ? g_out1[(size_t)node * 256 + k] : 0.f;
    }
    __syncthreads();
    int c = tid & 31;
#pragma unroll
    for (int half = 0; half < 2; half++) {
        int m = (tid >> 5) + half * 8;
        int node = node0 + m;
        if (node < NN) {
            float sacc = 0.f;
#pragma unroll 8
            for (int k = 0; k < 256; k++) sacc += hs[m][k] * ws[k * 32 + c];
            if (c < 16) g_xl2[node * 16 + c] = sacc;
            else        g_xr2[node * 16 + c - 16] = sacc;
        }
    }
}

// ------- layer-2 fused: 2 nodes per warp (16 lanes each), online softmax -----
__global__ void k_fused2(const float* __restrict__ att2, const float* __restrict__ b2,
                         float* __restrict__ dout) {
    int t = threadIdx.x;
    int lane = t & 31;
    int half = lane >> 4, c = lane & 15;
    int node = blockIdx.x * 16 + (t >> 5) * 2 + half;   // NN % 16 == 0 -> always valid
    int p0 = g_start[node], p1 = g_start[node + 1];
    int deg = p1 - p0;
    int dego = __shfl_xor_sync(0xFFFFFFFFu, deg, 16);
    int nit = deg > dego ? deg : dego;

    float xr = g_xr2[node * 16 + c];
    float at = att2[c];
    float m = -1e30f, den = 0.f, acc = 0.f;

    for (int i = 0; i < nit; i++) {
        bool val = i < deg;
        int p = val ? (p0 + i) : p0;
        int s = g_csr_src[p];
        float xl = g_xl2[s * 16 + c];
        float v = xl + xr;
        v = v > 0.f ? v : 0.2f * v;
        float sc = v * at;
        sc += __shfl_xor_sync(0xFFFFFFFFu, sc, 8);
        sc += __shfl_xor_sync(0xFFFFFFFFu, sc, 4);
        sc += __shfl_xor_sync(0xFFFFFFFFu, sc, 2);
        sc += __shfl_xor_sync(0xFFFFFFFFu, sc, 1);
        if (!val) sc = -1e38f;
        if (sc <= m) {
            float w = __expf(sc - m);
            den += w;
            acc += w * xl;
        } else {
            float sfac = __expf(m - sc);
            den = den * sfac + 1.f;
            acc = acc * sfac + xl;
            m = sc;
        }
    }
    float v = acc / (den + 1e-16f) + b2[c];
    dout[node * 16 + c] = v >= 0.f ? v : 0.01f * v;
}

// ---------------- launch ------------------------------------------------------
extern "C" void kernel_launch(void* const* d_in, const int* in_sizes, int n_in,
                              void* d_out, int out_size) {
    const float* x    = (const float*)d_in[0];
    const int*   ei   = (const int*)d_in[1];
    const float* W1l  = (const float*)d_in[2];
    const float* W1r  = (const float*)d_in[3];
    const float* att1 = (const float*)d_in[4];
    const float* b1   = (const float*)d_in[5];
    const float* W2l  = (const float*)d_in[6];
    const float* W2r  = (const float*)d_in[7];
    const float* att2 = (const float*)d_in[8];
    const float* b2   = (const float*)d_in[9];
    float* out = (float*)d_out;

    k_init<<<(NN + 255) / 256, 256>>>();
    k_hist<<<(EE / 4 + 255) / 256, 256>>>(ei);
    k_scan<<<1, 1024>>>();
    k_scatter<<<(ET + 255) / 256, 256>>>(ei);

    dim3 g1(4, (NN + 127) / 128);
    k_gemm1<<<g1, 256>>>(x, W1l, W1r);

    k_fused1<<<(NN + 7) / 8, 256>>>(att1, b1);

    k_gemm2<<<(NN + 15) / 16, 256>>>(W2l, W2r);

    k_fused2<<<NN / 16, 256>>>(att2, b2, out);
}

// round 10
// speedup vs baseline: 1.1287x; 1.0578x over previous
#include <cuda_runtime.h>
#include <cuda_fp16.h>
#include <math.h>
#include <stdint.h>

#define NN 50000
#define EE 640000
#define ET 690000   // EE + NN self loops

// ---------------- scratch (device globals) ----------------------------------
__device__ __half g_xl1h[(size_t)NN * 256];
__device__ __half g_xr1h[(size_t)NN * 256];
__device__ float  g_out1[(size_t)NN * 256];
__device__ float  g_xl2[NN * 16];
__device__ float  g_xr2[NN * 16];
__device__ int    g_deg[NN];
__device__ int    g_start[NN + 1];
__device__ int    g_cursor[NN];
__device__ int    g_csr_src[ET];

// ---------------- CSR construction ------------------------------------------
__global__ void k_init() {
    int i = blockIdx.x * 256 + threadIdx.x;
    if (i < NN) { g_deg[i] = 1; g_cursor[i] = 0; }   // deg=1: self loop pre-counted
}

__global__ void k_hist(const int* __restrict__ ei) {
    int e = (blockIdx.x * 256 + threadIdx.x) * 4;
    if (e + 4 <= EE) {
        int4 d = *(const int4*)(ei + EE + e);
        atomicAdd(&g_deg[d.x], 1);
        atomicAdd(&g_deg[d.y], 1);
        atomicAdd(&g_deg[d.z], 1);
        atomicAdd(&g_deg[d.w], 1);
    }
}

__global__ void k_scan() {
    __shared__ int sums[1024];
    int t = threadIdx.x;
    const int C = 49;                 // 49*1024 = 50176 >= NN
    int base = t * C;
    int s = 0;
    for (int i = 0; i < C; i++) { int idx = base + i; if (idx < NN) s += g_deg[idx]; }
    sums[t] = s;
    __syncthreads();
    for (int off = 1; off < 1024; off <<= 1) {
        int v = 0;
        if (t >= off) v = sums[t - off];
        __syncthreads();
        sums[t] += v;
        __syncthreads();
    }
    int run = (t == 0) ? 0 : sums[t - 1];
    for (int i = 0; i < C; i++) {
        int idx = base + i;
        if (idx < NN) { g_start[idx] = run; run += g_deg[idx]; }
    }
    if (t == 1023) g_start[NN] = ET;
}

__global__ void k_scatter(const int* __restrict__ ei) {
    int e = blockIdx.x * 256 + threadIdx.x;
    if (e >= ET) return;
    int s = (e < EE) ? ei[e] : e - EE;
    int d = (e < EE) ? ei[EE + e] : e - EE;
    int p = g_start[d] + atomicAdd(&g_cursor[d], 1);
    g_csr_src[p] = s;
}

// ---------------- fp16 mma helper ---------------------------------------------
__device__ __forceinline__ void mma_f16(float c[4], const uint32_t a[4], const uint32_t b[2]) {
    asm volatile(
        "mma.sync.aligned.m16n8k16.row.col.f32.f16.f16.f32 "
        "{%0,%1,%2,%3},{%4,%5,%6,%7},{%8,%9},{%0,%1,%2,%3};"
        : "+f"(c[0]), "+f"(c[1]), "+f"(c[2]), "+f"(c[3])
        : "r"(a[0]), "r"(a[1]), "r"(a[2]), "r"(a[3]), "r"(b[0]), "r"(b[1]));
}

// ---------------- GEMM1 (fp16 tensor core): X[NN,128] @ [W1l|W1r][128,512] ---
// 128x128 block tile, BK=32, 8 warps (2m x 4n), warp tile 64x32, m16n8k16.
// As: [m][k] half, padded stride 40 halves (conflict-free frag loads)
// Bs: [k][n] half, padded stride 136 halves
#define LDAH 40
#define LDBH 136
__global__ void __launch_bounds__(256, 2) k_gemm1(const float* __restrict__ X,
                                                  const float* __restrict__ Wl,
                                                  const float* __restrict__ Wr) {
    __shared__ __half As[128 * LDAH];
    __shared__ __half Bs[32 * LDBH];
    const int bm = blockIdx.y * 128;
    const int bn = blockIdx.x * 128;
    const float* Bsrc = (bn < 256) ? Wl : Wr;
    const int bnl = bn & 255;

    const int tid = threadIdx.x;
    const int wid = tid >> 5, lane = tid & 31;
    const int wm = wid >> 2, wn = wid & 3;
    const int g = lane >> 2, tg = lane & 3;

    float acc[4][4][4];
#pragma unroll
    for (int mt = 0; mt < 4; mt++)
#pragma unroll
        for (int nt = 0; nt < 4; nt++)
#pragma unroll
            for (int r = 0; r < 4; r++) acc[mt][nt][r] = 0.f;

    const uint16_t* BsU = (const uint16_t*)Bs;

    for (int k0 = 0; k0 < 128; k0 += 32) {
        // stage A: As[m][k] = fp16(X[bm+m][k0+k])
#pragma unroll
        for (int it = 0; it < 4; it++) {
            int idx = tid + it * 256;
            int m = idx >> 3, kq = (idx & 7) * 4;
            float4 v = make_float4(0.f, 0.f, 0.f, 0.f);
            int row = bm + m;
            if (row < NN) v = *(const float4*)(X + (size_t)row * 128 + k0 + kq);
            __half2 h0 = __floats2half2_rn(v.x, v.y);
            __half2 h1 = __floats2half2_rn(v.z, v.w);
            *(__half2*)(As + m * LDAH + kq)     = h0;
            *(__half2*)(As + m * LDAH + kq + 2) = h1;
        }
        // stage B: Bs[k][n] = fp16(W[k0+k][bnl+n])
#pragma unroll
        for (int it = 0; it < 4; it++) {
            int idx = tid + it * 256;
            int k = idx >> 5, nf = (idx & 31) * 4;
            float4 v = *(const float4*)(Bsrc + (size_t)(k0 + k) * 256 + bnl + nf);
            *(__half2*)(Bs + k * LDBH + nf)     = __floats2half2_rn(v.x, v.y);
            *(__half2*)(Bs + k * LDBH + nf + 2) = __floats2half2_rn(v.z, v.w);
        }
        __syncthreads();

#pragma unroll
        for (int ks = 0; ks < 2; ks++) {
            int kb = ks * 16;
            uint32_t a[4][4], b[4][2];
#pragma unroll
            for (int mt = 0; mt < 4; mt++) {
                int rb = wm * 64 + mt * 16 + g;
                a[mt][0] = *(const uint32_t*)(As + rb * LDAH + kb + 2 * tg);
                a[mt][1] = *(const uint32_t*)(As + (rb + 8) * LDAH + kb + 2 * tg);
                a[mt][2] = *(const uint32_t*)(As + rb * LDAH + kb + 2 * tg + 8);
                a[mt][3] = *(const uint32_t*)(As + (rb + 8) * LDAH + kb + 2 * tg + 8);
            }
#pragma unroll
            for (int nt = 0; nt < 4; nt++) {
                int cb = wn * 32 + nt * 8 + g;
                uint32_t lo0 = BsU[(kb + 2 * tg) * LDBH + cb];
                uint32_t hi0 = BsU[(kb + 2 * tg + 1) * LDBH + cb];
                uint32_t lo1 = BsU[(kb + 2 * tg + 8) * LDBH + cb];
                uint32_t hi1 = BsU[(kb + 2 * tg + 9) * LDBH + cb];
                b[nt][0] = lo0 | (hi0 << 16);
                b[nt][1] = lo1 | (hi1 << 16);
            }
#pragma unroll
            for (int mt = 0; mt < 4; mt++)
#pragma unroll
                for (int nt = 0; nt < 4; nt++)
                    mma_f16(acc[mt][nt], a[mt], b[nt]);
        }
        __syncthreads();
    }

    __half2* dst = (__half2*)((bn < 256) ? g_xl1h : g_xr1h);
#pragma unroll
    for (int mt = 0; mt < 4; mt++) {
        int row0 = bm + wm * 64 + mt * 16 + g;
#pragma unroll
        for (int nt = 0; nt < 4; nt++) {
            int col = bnl + wn * 32 + nt * 8 + 2 * tg;   // even
            if (row0 < NN)
                dst[((size_t)row0 * 256 + col) >> 1] =
                    __floats2half2_rn(acc[mt][nt][0], acc[mt][nt][1]);
            if (row0 + 8 < NN)
                dst[((size_t)(row0 + 8) * 256 + col) >> 1] =
                    __floats2half2_rn(acc[mt][nt][2], acc[mt][nt][3]);
        }
    }
}

// ---- layer-1 fused: score + online softmax + aggregate + b1 + ELU -----------
// warp per node; lane = h*4+q owns 8 contiguous (fp16) floats of head h.
__global__ void k_fused1(const float* __restrict__ att1, const float* __restrict__ b1) {
    int t = threadIdx.x;
    int node = blockIdx.x * 8 + (t >> 5);
    if (node >= NN) return;
    int lane = t & 31, h = lane >> 2, q = lane & 3;
    int base = h * 32 + q * 8;
    int p0 = g_start[node], p1 = g_start[node + 1];

    float4 at0 = *(const float4*)(att1 + base);
    float4 at1 = *(const float4*)(att1 + base + 4);

    // xr: 8 fp16 -> fp32
    uint4 rr = *(const uint4*)(g_xr1h + (size_t)node * 256 + base);
    float2 xrA = __half22float2(*(__half2*)&rr.x);
    float2 xrB = __half22float2(*(__half2*)&rr.y);
    float2 xrC = __half22float2(*(__half2*)&rr.z);
    float2 xrD = __half22float2(*(__half2*)&rr.w);

    float m = -1e30f, den = 0.f;
    float acc[8];
#pragma unroll
    for (int i = 0; i < 8; i++) acc[i] = 0.f;

    for (int p = p0; p < p1; p++) {
        int s = g_csr_src[p];
        uint4 raw = *(const uint4*)(g_xl1h + (size_t)s * 256 + base);
        float2 lA = __half22float2(*(__half2*)&raw.x);
        float2 lB = __half22float2(*(__half2*)&raw.y);
        float2 lC = __half22float2(*(__half2*)&raw.z);
        float2 lD = __half22float2(*(__half2*)&raw.w);

        float v, sc = 0.f;
        v = lA.x + xrA.x; v = v > 0.f ? v : 0.2f * v; sc += at0.x * v;
        v = lA.y + xrA.y; v = v > 0.f ? v : 0.2f * v; sc += at0.y * v;
        v = lB.x + xrB.x; v = v > 0.f ? v : 0.2f * v; sc += at0.z * v;
        v = lB.y + xrB.y; v = v > 0.f ? v : 0.2f * v; sc += at0.w * v;
        v = lC.x + xrC.x; v = v > 0.f ? v : 0.2f * v; sc += at1.x * v;
        v = lC.y + xrC.y; v = v > 0.f ? v : 0.2f * v; sc += at1.y * v;
        v = lD.x + xrD.x; v = v > 0.f ? v : 0.2f * v; sc += at1.z * v;
        v = lD.y + xrD.y; v = v > 0.f ? v : 0.2f * v; sc += at1.w * v;
        sc += __shfl_xor_sync(0xFFFFFFFFu, sc, 1);
        sc += __shfl_xor_sync(0xFFFFFFFFu, sc, 2);

        if (sc <= m) {
            float w = __expf(sc - m);
            den += w;
            acc[0] += w * lA.x; acc[1] += w * lA.y; acc[2] += w * lB.x; acc[3] += w * lB.y;
            acc[4] += w * lC.x; acc[5] += w * lC.y; acc[6] += w * lD.x; acc[7] += w * lD.y;
        } else {
            float sfac = __expf(m - sc);
            den = den * sfac + 1.f;
            acc[0] = acc[0] * sfac + lA.x; acc[1] = acc[1] * sfac + lA.y;
            acc[2] = acc[2] * sfac + lB.x; acc[3] = acc[3] * sfac + lB.y;
            acc[4] = acc[4] * sfac + lC.x; acc[5] = acc[5] * sfac + lC.y;
            acc[6] = acc[6] * sfac + lD.x; acc[7] = acc[7] * sfac + lD.y;
            m = sc;
        }
    }

    float inv = 1.f / (den + 1e-16f);
    float4 bb0 = *(const float4*)(b1 + base);
    float4 bb1 = *(const float4*)(b1 + base + 4);
    float o[8];
    o[0] = acc[0] * inv + bb0.x; o[1] = acc[1] * inv + bb0.y;
    o[2] = acc[2] * inv + bb0.z; o[3] = acc[3] * inv + bb0.w;
    o[4] = acc[4] * inv + bb1.x; o[5] = acc[5] * inv + bb1.y;
    o[6] = acc[6] * inv + bb1.z; o[7] = acc[7] * inv + bb1.w;
#pragma unroll
    for (int i = 0; i < 8; i++) o[i] = o[i] > 0.f ? o[i] : expm1f(o[i]);
    float* dst = g_out1 + (size_t)node * 256 + base;
    *(float4*)(dst)     = make_float4(o[0], o[1], o[2], o[3]);
    *(float4*)(dst + 4) = make_float4(o[4], o[5], o[6], o[7]);
}

// ---------------- GEMM2: h[NN,256] @ [W2l | W2r][256,32] --------------------
__global__ void k_gemm2(const float* __restrict__ Wl, const float* __restrict__ Wr) {
    __shared__ float ws[256 * 32];
    __shared__ float hs[16][256];
    int tid = threadIdx.x;
    for (int i = tid; i < 256 * 32; i += 256) {
        int k = i >> 5, c = i & 31;
        ws[i] = (c < 16) ? Wl[k * 16 + c] : Wr[k * 16 + c - 16];
    }
    int node0 = blockIdx.x * 16;
    for (int i = tid; i < 16 * 256; i += 256) {
        int m = i >> 8, k = i & 255;
        int node = node0 + m;
        hs[m][k] = (node < NN) ? g_out1[(size_t)node * 256 + k] : 0.f;
    }
    __syncthreads();
    int c = tid & 31;
#pragma unroll
    for (int half = 0; half < 2; half++) {
        int m = (tid >> 5) + half * 8;
        int node = node0 + m;
        if (node < NN) {
            float sacc = 0.f;
#pragma unroll 8
            for (int k = 0; k < 256; k++) sacc += hs[m][k] * ws[k * 32 + c];
            if (c < 16) g_xl2[node * 16 + c] = sacc;
            else        g_xr2[node * 16 + c - 16] = sacc;
        }
    }
}

// ------- layer-2 fused: 2 nodes per warp (16 lanes each), online softmax -----
__global__ void k_fused2(const float* __restrict__ att2, const float* __restrict__ b2,
                         float* __restrict__ dout) {
    int t = threadIdx.x;
    int lane = t & 31;
    int half = lane >> 4, c = lane & 15;
    int node = blockIdx.x * 16 + (t >> 5) * 2 + half;   // NN % 16 == 0 -> always valid
    int p0 = g_start[node], p1 = g_start[node + 1];
    int deg = p1 - p0;
    int dego = __shfl_xor_sync(0xFFFFFFFFu, deg, 16);
    int nit = deg > dego ? deg : dego;

    float xr = g_xr2[node * 16 + c];
    float at = att2[c];
    float m = -1e30f, den = 0.f, acc = 0.f;

    for (int i = 0; i < nit; i++) {
        bool val = i < deg;
        int p = val ? (p0 + i) : p0;
        int s = g_csr_src[p];
        float xl = g_xl2[s * 16 + c];
        float v = xl + xr;
        v = v > 0.f ? v : 0.2f * v;
        float sc = v * at;
        sc += __shfl_xor_sync(0xFFFFFFFFu, sc, 8);
        sc += __shfl_xor_sync(0xFFFFFFFFu, sc, 4);
        sc += __shfl_xor_sync(0xFFFFFFFFu, sc, 2);
        sc += __shfl_xor_sync(0xFFFFFFFFu, sc, 1);
        if (!val) sc = -1e38f;
        if (sc <= m) {
            float w = __expf(sc - m);
            den += w;
            acc += w * xl;
        } else {
            float sfac = __expf(m - sc);
            den = den * sfac + 1.f;
            acc = acc * sfac + xl;
            m = sc;
        }
    }
    float v = acc / (den + 1e-16f) + b2[c];
    dout[node * 16 + c] = v >= 0.f ? v : 0.01f * v;
}

// ---------------- launch ------------------------------------------------------
extern "C" void kernel_launch(void* const* d_in, const int* in_sizes, int n_in,
                              void* d_out, int out_size) {
    const float* x    = (const float*)d_in[0];
    const int*   ei   = (const int*)d_in[1];
    const float* W1l  = (const float*)d_in[2];
    const float* W1r  = (const float*)d_in[3];
    const float* att1 = (const float*)d_in[4];
    const float* b1   = (const float*)d_in[5];
    const float* W2l  = (const float*)d_in[6];
    const float* W2r  = (const float*)d_in[7];
    const float* att2 = (const float*)d_in[8];
    const float* b2   = (const float*)d_in[9];
    float* out = (float*)d_out;

    k_init<<<(NN + 255) / 256, 256>>>();
    k_hist<<<(EE / 4 + 255) / 256, 256>>>(ei);
    k_scan<<<1, 1024>>>();
    k_scatter<<<(ET + 255) / 256, 256>>>(ei);

    dim3 g1(4, (NN + 127) / 128);
    k_gemm1<<<g1, 256>>>(x, W1l, W1r);

    k_fused1<<<(NN + 7) / 8, 256>>>(att1, b1);

    k_gemm2<<<(NN + 15) / 16, 256>>>(W2l, W2r);

    k_fused2<<<NN / 16, 256>>>(att2, b2, out);
}

// round 11
// speedup vs baseline: 1.1839x; 1.0489x over previous
#include <cuda_runtime.h>
#include <cuda_fp16.h>
#include <math.h>
#include <stdint.h>

#define NN 50000
#define EE 640000
#define ET 690000   // EE + NN self loops

// ---------------- scratch (device globals) ----------------------------------
__device__ __half g_xl1h[(size_t)NN * 256];
__device__ __half g_xr1h[(size_t)NN * 256];
__device__ __half g_h1[(size_t)NN * 256];      // layer-1 output (post-ELU), fp16
__device__ float  g_xl2[NN * 16];
__device__ float  g_xr2[NN * 16];
__device__ int    g_deg[NN];
__device__ int    g_start[NN + 1];
__device__ int    g_cursor[NN];
__device__ int    g_csr_src[ET];

// ---------------- CSR construction ------------------------------------------
__global__ void k_init() {
    int i = blockIdx.x * 256 + threadIdx.x;
    if (i < NN) { g_deg[i] = 1; g_cursor[i] = 0; }   // deg=1: self loop pre-counted
}

__global__ void k_hist(const int* __restrict__ ei) {
    int e = (blockIdx.x * 256 + threadIdx.x) * 4;
    if (e + 4 <= EE) {
        int4 d = *(const int4*)(ei + EE + e);
        atomicAdd(&g_deg[d.x], 1);
        atomicAdd(&g_deg[d.y], 1);
        atomicAdd(&g_deg[d.z], 1);
        atomicAdd(&g_deg[d.w], 1);
    }
}

__global__ void k_scan() {
    __shared__ int sums[1024];
    int t = threadIdx.x;
    const int C = 49;                 // 49*1024 = 50176 >= NN
    int base = t * C;
    int s = 0;
    for (int i = 0; i < C; i++) { int idx = base + i; if (idx < NN) s += g_deg[idx]; }
    sums[t] = s;
    __syncthreads();
    for (int off = 1; off < 1024; off <<= 1) {
        int v = 0;
        if (t >= off) v = sums[t - off];
        __syncthreads();
        sums[t] += v;
        __syncthreads();
    }
    int run = (t == 0) ? 0 : sums[t - 1];
    for (int i = 0; i < C; i++) {
        int idx = base + i;
        if (idx < NN) { g_start[idx] = run; run += g_deg[idx]; }
    }
    if (t == 1023) g_start[NN] = ET;
}

__global__ void k_scatter(const int* __restrict__ ei) {
    int e = blockIdx.x * 256 + threadIdx.x;
    if (e >= ET) return;
    int s = (e < EE) ? ei[e] : e - EE;
    int d = (e < EE) ? ei[EE + e] : e - EE;
    int p = g_start[d] + atomicAdd(&g_cursor[d], 1);
    g_csr_src[p] = s;
}

// ---------------- fp16 mma helper ---------------------------------------------
__device__ __forceinline__ void mma_f16(float c[4], const uint32_t a[4], const uint32_t b[2]) {
    asm volatile(
        "mma.sync.aligned.m16n8k16.row.col.f32.f16.f16.f32 "
        "{%0,%1,%2,%3},{%4,%5,%6,%7},{%8,%9},{%0,%1,%2,%3};"
        : "+f"(c[0]), "+f"(c[1]), "+f"(c[2]), "+f"(c[3])
        : "r"(a[0]), "r"(a[1]), "r"(a[2]), "r"(a[3]), "r"(b[0]), "r"(b[1]));
}

// ---------------- GEMM1 (fp16 TC, BK=64): X[NN,128] @ [W1l|W1r][128,512] -----
// 128x128 block tile, BK=64 (2 slabs), 8 warps (2m x 4n), warp tile 64x32.
#define LDAH 72     // 64 + 8 halves
#define LDBH 136
__global__ void __launch_bounds__(256, 2) k_gemm1(const float* __restrict__ X,
                                                  const float* __restrict__ Wl,
                                                  const float* __restrict__ Wr) {
    __shared__ __half As[128 * LDAH];   // [m][k]
    __shared__ __half Bs[64 * LDBH];    // [k][n]
    const int bm = blockIdx.y * 128;
    const int bn = blockIdx.x * 128;
    const float* Bsrc = (bn < 256) ? Wl : Wr;
    const int bnl = bn & 255;

    const int tid = threadIdx.x;
    const int wid = tid >> 5, lane = tid & 31;
    const int wm = wid >> 2, wn = wid & 3;
    const int g = lane >> 2, tg = lane & 3;

    float acc[4][4][4];
#pragma unroll
    for (int mt = 0; mt < 4; mt++)
#pragma unroll
        for (int nt = 0; nt < 4; nt++)
#pragma unroll
            for (int r = 0; r < 4; r++) acc[mt][nt][r] = 0.f;

    const uint16_t* BsU = (const uint16_t*)Bs;

    for (int k0 = 0; k0 < 128; k0 += 64) {
        // stage A: As[m][k] = fp16(X[bm+m][k0+k]), 128m x 64k
#pragma unroll
        for (int it = 0; it < 8; it++) {
            int idx = tid + it * 256;           // 0..2047
            int m = idx >> 4, kq = (idx & 15) * 4;
            float4 v = make_float4(0.f, 0.f, 0.f, 0.f);
            int row = bm + m;
            if (row < NN) v = *(const float4*)(X + (size_t)row * 128 + k0 + kq);
            *(__half2*)(As + m * LDAH + kq)     = __floats2half2_rn(v.x, v.y);
            *(__half2*)(As + m * LDAH + kq + 2) = __floats2half2_rn(v.z, v.w);
        }
        // stage B: Bs[k][n] = fp16(W[k0+k][bnl+n]), 64k x 128n
#pragma unroll
        for (int it = 0; it < 8; it++) {
            int idx = tid + it * 256;
            int k = idx >> 5, nf = (idx & 31) * 4;
            float4 v = *(const float4*)(Bsrc + (size_t)(k0 + k) * 256 + bnl + nf);
            *(__half2*)(Bs + k * LDBH + nf)     = __floats2half2_rn(v.x, v.y);
            *(__half2*)(Bs + k * LDBH + nf + 2) = __floats2half2_rn(v.z, v.w);
        }
        __syncthreads();

#pragma unroll
        for (int ks = 0; ks < 4; ks++) {
            int kb = ks * 16;
            uint32_t a[4][4], b[4][2];
#pragma unroll
            for (int mt = 0; mt < 4; mt++) {
                int rb = wm * 64 + mt * 16 + g;
                a[mt][0] = *(const uint32_t*)(As + rb * LDAH + kb + 2 * tg);
                a[mt][1] = *(const uint32_t*)(As + (rb + 8) * LDAH + kb + 2 * tg);
                a[mt][2] = *(const uint32_t*)(As + rb * LDAH + kb + 2 * tg + 8);
                a[mt][3] = *(const uint32_t*)(As + (rb + 8) * LDAH + kb + 2 * tg + 8);
            }
#pragma unroll
            for (int nt = 0; nt < 4; nt++) {
                int cb = wn * 32 + nt * 8 + g;
                uint32_t lo0 = BsU[(kb + 2 * tg) * LDBH + cb];
                uint32_t hi0 = BsU[(kb + 2 * tg + 1) * LDBH + cb];
                uint32_t lo1 = BsU[(kb + 2 * tg + 8) * LDBH + cb];
                uint32_t hi1 = BsU[(kb + 2 * tg + 9) * LDBH + cb];
                b[nt][0] = lo0 | (hi0 << 16);
                b[nt][1] = lo1 | (hi1 << 16);
            }
#pragma unroll
            for (int mt = 0; mt < 4; mt++)
#pragma unroll
                for (int nt = 0; nt < 4; nt++)
                    mma_f16(acc[mt][nt], a[mt], b[nt]);
        }
        __syncthreads();
    }

    __half2* dst = (__half2*)((bn < 256) ? g_xl1h : g_xr1h);
#pragma unroll
    for (int mt = 0; mt < 4; mt++) {
        int row0 = bm + wm * 64 + mt * 16 + g;
#pragma unroll
        for (int nt = 0; nt < 4; nt++) {
            int col = bnl + wn * 32 + nt * 8 + 2 * tg;   // even
            if (row0 < NN)
                dst[((size_t)row0 * 256 + col) >> 1] =
                    __floats2half2_rn(acc[mt][nt][0], acc[mt][nt][1]);
            if (row0 + 8 < NN)
                dst[((size_t)(row0 + 8) * 256 + col) >> 1] =
                    __floats2half2_rn(acc[mt][nt][2], acc[mt][nt][3]);
        }
    }
}

// ---- layer-1 fused: score + online softmax + aggregate + b1 + ELU -----------
// warp per node; lane = h*4+q owns 8 contiguous (fp16) floats of head h.
__global__ void k_fused1(const float* __restrict__ att1, const float* __restrict__ b1) {
    int t = threadIdx.x;
    int node = blockIdx.x * 8 + (t >> 5);
    if (node >= NN) return;
    int lane = t & 31, h = lane >> 2, q = lane & 3;
    int base = h * 32 + q * 8;
    int p0 = g_start[node], p1 = g_start[node + 1];

    float4 at0 = *(const float4*)(att1 + base);
    float4 at1 = *(const float4*)(att1 + base + 4);

    uint4 rr = *(const uint4*)(g_xr1h + (size_t)node * 256 + base);
    float2 xrA = __half22float2(*(__half2*)&rr.x);
    float2 xrB = __half22float2(*(__half2*)&rr.y);
    float2 xrC = __half22float2(*(__half2*)&rr.z);
    float2 xrD = __half22float2(*(__half2*)&rr.w);

    float m = -1e30f, den = 0.f;
    float acc[8];
#pragma unroll
    for (int i = 0; i < 8; i++) acc[i] = 0.f;

    for (int p = p0; p < p1; p++) {
        int s = g_csr_src[p];
        uint4 raw = *(const uint4*)(g_xl1h + (size_t)s * 256 + base);
        float2 lA = __half22float2(*(__half2*)&raw.x);
        float2 lB = __half22float2(*(__half2*)&raw.y);
        float2 lC = __half22float2(*(__half2*)&raw.z);
        float2 lD = __half22float2(*(__half2*)&raw.w);

        float v, sc = 0.f;
        v = lA.x + xrA.x; v = v > 0.f ? v : 0.2f * v; sc += at0.x * v;
        v = lA.y + xrA.y; v = v > 0.f ? v : 0.2f * v; sc += at0.y * v;
        v = lB.x + xrB.x; v = v > 0.f ? v : 0.2f * v; sc += at0.z * v;
        v = lB.y + xrB.y; v = v > 0.f ? v : 0.2f * v; sc += at0.w * v;
        v = lC.x + xrC.x; v = v > 0.f ? v : 0.2f * v; sc += at1.x * v;
        v = lC.y + xrC.y; v = v > 0.f ? v : 0.2f * v; sc += at1.y * v;
        v = lD.x + xrD.x; v = v > 0.f ? v : 0.2f * v; sc += at1.z * v;
        v = lD.y + xrD.y; v = v > 0.f ? v : 0.2f * v; sc += at1.w * v;
        sc += __shfl_xor_sync(0xFFFFFFFFu, sc, 1);
        sc += __shfl_xor_sync(0xFFFFFFFFu, sc, 2);

        if (sc <= m) {
            float w = __expf(sc - m);
            den += w;
            acc[0] += w * lA.x; acc[1] += w * lA.y; acc[2] += w * lB.x; acc[3] += w * lB.y;
            acc[4] += w * lC.x; acc[5] += w * lC.y; acc[6] += w * lD.x; acc[7] += w * lD.y;
        } else {
            float sfac = __expf(m - sc);
            den = den * sfac + 1.f;
            acc[0] = acc[0] * sfac + lA.x; acc[1] = acc[1] * sfac + lA.y;
            acc[2] = acc[2] * sfac + lB.x; acc[3] = acc[3] * sfac + lB.y;
            acc[4] = acc[4] * sfac + lC.x; acc[5] = acc[5] * sfac + lC.y;
            acc[6] = acc[6] * sfac + lD.x; acc[7] = acc[7] * sfac + lD.y;
            m = sc;
        }
    }

    float inv = 1.f / (den + 1e-16f);
    float4 bb0 = *(const float4*)(b1 + base);
    float4 bb1 = *(const float4*)(b1 + base + 4);
    float o[8];
    o[0] = acc[0] * inv + bb0.x; o[1] = acc[1] * inv + bb0.y;
    o[2] = acc[2] * inv + bb0.z; o[3] = acc[3] * inv + bb0.w;
    o[4] = acc[4] * inv + bb1.x; o[5] = acc[5] * inv + bb1.y;
    o[6] = acc[6] * inv + bb1.z; o[7] = acc[7] * inv + bb1.w;
#pragma unroll
    for (int i = 0; i < 8; i++) o[i] = o[i] > 0.f ? o[i] : expm1f(o[i]);

    uint4 packed;
    *(__half2*)&packed.x = __floats2half2_rn(o[0], o[1]);
    *(__half2*)&packed.y = __floats2half2_rn(o[2], o[3]);
    *(__half2*)&packed.z = __floats2half2_rn(o[4], o[5]);
    *(__half2*)&packed.w = __floats2half2_rn(o[6], o[7]);
    *(uint4*)(g_h1 + (size_t)node * 256 + base) = packed;
}

// ---------------- GEMM2: h[NN,256](fp16) @ [W2l | W2r][256,32] ---------------
__global__ void k_gemm2(const float* __restrict__ Wl, const float* __restrict__ Wr) {
    __shared__ float ws[256 * 32];
    __shared__ float hs[16][256];
    int tid = threadIdx.x;
    for (int i = tid; i < 256 * 32; i += 256) {
        int k = i >> 5, c = i & 31;
        ws[i] = (c < 16) ? Wl[k * 16 + c] : Wr[k * 16 + c - 16];
    }
    int node0 = blockIdx.x * 16;
    const __half2* hp = (const __half2*)g_h1;
    for (int i = tid; i < 16 * 128; i += 256) {
        int m = i >> 7, kk = (i & 127) * 2;
        int node = node0 + m;
        float2 v = make_float2(0.f, 0.f);
        if (node < NN) v = __half22float2(hp[((size_t)node * 256 + kk) >> 1]);
        hs[m][kk] = v.x;
        hs[m][kk + 1] = v.y;
    }
    __syncthreads();
    int c = tid & 31;
#pragma unroll
    for (int half = 0; half < 2; half++) {
        int m = (tid >> 5) + half * 8;
        int node = node0 + m;
        if (node < NN) {
            float sacc = 0.f;
#pragma unroll 8
            for (int k = 0; k < 256; k++) sacc += hs[m][k] * ws[k * 32 + c];
            if (c < 16) g_xl2[node * 16 + c] = sacc;
            else        g_xr2[node * 16 + c - 16] = sacc;
        }
    }
}

// ------- layer-2 fused: 2 nodes per warp (16 lanes each), online softmax -----
__global__ void k_fused2(const float* __restrict__ att2, const float* __restrict__ b2,
                         float* __restrict__ dout) {
    int t = threadIdx.x;
    int lane = t & 31;
    int half = lane >> 4, c = lane & 15;
    int node = blockIdx.x * 16 + (t >> 5) * 2 + half;   // NN % 16 == 0 -> always valid
    int p0 = g_start[node], p1 = g_start[node + 1];
    int deg = p1 - p0;
    int dego = __shfl_xor_sync(0xFFFFFFFFu, deg, 16);
    int nit = deg > dego ? deg : dego;

    float xr = g_xr2[node * 16 + c];
    float at = att2[c];
    float m = -1e30f, den = 0.f, acc = 0.f;

    for (int i = 0; i < nit; i++) {
        bool val = i < deg;
        int p = val ? (p0 + i) : p0;
        int s = g_csr_src[p];
        float xl = g_xl2[s * 16 + c];
        float v = xl + xr;
        v = v > 0.f ? v : 0.2f * v;
        float sc = v * at;
        sc += __shfl_xor_sync(0xFFFFFFFFu, sc, 8);
        sc += __shfl_xor_sync(0xFFFFFFFFu, sc, 4);
        sc += __shfl_xor_sync(0xFFFFFFFFu, sc, 2);
        sc += __shfl_xor_sync(0xFFFFFFFFu, sc, 1);
        if (!val) sc = -1e38f;
        if (sc <= m) {
            float w = __expf(sc - m);
            den += w;
            acc += w * xl;
        } else {
            float sfac = __expf(m - sc);
            den = den * sfac + 1.f;
            acc = acc * sfac + xl;
            m = sc;
        }
    }
    float v = acc / (den + 1e-16f) + b2[c];
    dout[node * 16 + c] = v >= 0.f ? v : 0.01f * v;
}

// ---------------- launch ------------------------------------------------------
extern "C" void kernel_launch(void* const* d_in, const int* in_sizes, int n_in,
                              void* d_out, int out_size) {
    const float* x    = (const float*)d_in[0];
    const int*   ei   = (const int*)d_in[1];
    const float* W1l  = (const float*)d_in[2];
    const float* W1r  = (const float*)d_in[3];
    const float* att1 = (const float*)d_in[4];
    const float* b1   = (const float*)d_in[5];
    const float* W2l  = (const float*)d_in[6];
    const float* W2r  = (const float*)d_in[7];
    const float* att2 = (const float*)d_in[8];
    const float* b2   = (const float*)d_in[9];
    float* out = (float*)d_out;

    k_init<<<(NN + 255) / 256, 256>>>();
    k_hist<<<(EE / 4 + 255) / 256, 256>>>(ei);
    k_scan<<<1, 1024>>>();
    k_scatter<<<(ET + 255) / 256, 256>>>(ei);

    dim3 g1(4, (NN + 127) / 128);
    k_gemm1<<<g1, 256>>>(x, W1l, W1r);

    k_fused1<<<(NN + 7) / 8, 256>>>(att1, b1);

    k_gemm2<<<(NN + 15) / 16, 256>>>(W2l, W2r);

    k_fused2<<<NN / 16, 256>>>(att2, b2, out);
}

// round 12
// speedup vs baseline: 1.2091x; 1.0213x over previous
#include <cuda_runtime.h>
#include <cuda_fp16.h>
#include <math.h>
#include <stdint.h>

#define NN 50000
#define EE 640000
#define ET 690000   // EE + NN self loops

// ---------------- scratch (device globals) ----------------------------------
__device__ __half g_xh[(size_t)NN * 128];      // X in fp16
__device__ __half g_wlh[128 * 256];            // W1l fp16
__device__ __half g_wrh[128 * 256];            // W1r fp16
__device__ __half g_xl1h[(size_t)NN * 256];
__device__ __half g_xr1h[(size_t)NN * 256];
__device__ __half g_h1[(size_t)NN * 256];      // layer-1 output (post-ELU), fp16
__device__ float  g_xl2[NN * 16];
__device__ float  g_xr2[NN * 16];
__device__ int    g_deg[NN];
__device__ int    g_start[NN + 1];
__device__ int    g_cursor[NN];
__device__ int    g_csr_src[ET];

// ---------------- CSR construction ------------------------------------------
__global__ void k_init() {
    int i = blockIdx.x * 256 + threadIdx.x;
    if (i < NN) { g_deg[i] = 1; g_cursor[i] = 0; }   // deg=1: self loop pre-counted
}

__global__ void k_hist(const int* __restrict__ ei) {
    int e = (blockIdx.x * 256 + threadIdx.x) * 4;
    if (e + 4 <= EE) {
        int4 d = *(const int4*)(ei + EE + e);
        atomicAdd(&g_deg[d.x], 1);
        atomicAdd(&g_deg[d.y], 1);
        atomicAdd(&g_deg[d.z], 1);
        atomicAdd(&g_deg[d.w], 1);
    }
}

__global__ void k_scan() {
    __shared__ int sums[1024];
    int t = threadIdx.x;
    const int C = 49;                 // 49*1024 = 50176 >= NN
    int base = t * C;
    int s = 0;
    for (int i = 0; i < C; i++) { int idx = base + i; if (idx < NN) s += g_deg[idx]; }
    sums[t] = s;
    __syncthreads();
    for (int off = 1; off < 1024; off <<= 1) {
        int v = 0;
        if (t >= off) v = sums[t - off];
        __syncthreads();
        sums[t] += v;
        __syncthreads();
    }
    int run = (t == 0) ? 0 : sums[t - 1];
    for (int i = 0; i < C; i++) {
        int idx = base + i;
        if (idx < NN) { g_start[idx] = run; run += g_deg[idx]; }
    }
    if (t == 1023) g_start[NN] = ET;
}

__global__ void k_scatter(const int* __restrict__ ei) {
    int e = blockIdx.x * 256 + threadIdx.x;
    if (e >= ET) return;
    int s = (e < EE) ? ei[e] : e - EE;
    int d = (e < EE) ? ei[EE + e] : e - EE;
    int p = g_start[d] + atomicAdd(&g_cursor[d], 1);
    g_csr_src[p] = s;
}

// ---------------- fp16 conversion of X, W1l, W1r -----------------------------
#define NX (NN * 128 / 8)          // 800000
#define NW (128 * 256 / 8)         // 4096
__global__ void k_cvt(const float* __restrict__ X,
                      const float* __restrict__ Wl,
                      const float* __restrict__ Wr) {
    int i = blockIdx.x * 256 + threadIdx.x;
    const float* src;
    __half* dst;
    int j;
    if (i < NX)              { src = X;  dst = g_xh;  j = i; }
    else if (i < NX + NW)    { src = Wl; dst = g_wlh; j = i - NX; }
    else if (i < NX + 2*NW)  { src = Wr; dst = g_wrh; j = i - NX - NW; }
    else return;
    float4 a = *(const float4*)(src + (size_t)j * 8);
    float4 b = *(const float4*)(src + (size_t)j * 8 + 4);
    uint4 o;
    *(__half2*)&o.x = __floats2half2_rn(a.x, a.y);
    *(__half2*)&o.y = __floats2half2_rn(a.z, a.w);
    *(__half2*)&o.z = __floats2half2_rn(b.x, b.y);
    *(__half2*)&o.w = __floats2half2_rn(b.z, b.w);
    *(uint4*)(dst + (size_t)j * 8) = o;
}

// ---------------- fp16 mma helper ---------------------------------------------
__device__ __forceinline__ void mma_f16(float c[4], const uint32_t a[4], const uint32_t b[2]) {
    asm volatile(
        "mma.sync.aligned.m16n8k16.row.col.f32.f16.f16.f32 "
        "{%0,%1,%2,%3},{%4,%5,%6,%7},{%8,%9},{%0,%1,%2,%3};"
        : "+f"(c[0]), "+f"(c[1]), "+f"(c[2]), "+f"(c[3])
        : "r"(a[0]), "r"(a[1]), "r"(a[2]), "r"(a[3]), "r"(b[0]), "r"(b[1]));
}

__device__ __forceinline__ void cpa16(void* smem_ptr, const void* gmem_ptr, int src_sz) {
    uint32_t saddr = (uint32_t)__cvta_generic_to_shared(smem_ptr);
    asm volatile("cp.async.cg.shared.global [%0], [%1], 16, %2;"
                 :: "r"(saddr), "l"(gmem_ptr), "r"(src_sz));
}

// ---------------- GEMM1 (fp16 TC, cp.async 2-stage, BK=32) -------------------
// 128x128 block tile, 4 K-slabs of 32, 8 warps (2m x 4n), warp tile 64x32.
#define LDAH 40
#define LDBH 136
__global__ void __launch_bounds__(256, 2) k_gemm1() {
    __shared__ __half As[2][128 * LDAH];   // [m][k]
    __shared__ __half Bs[2][32 * LDBH];    // [k][n]
    const int bm = blockIdx.y * 128;
    const int bn = blockIdx.x * 128;
    const __half* Bsrc = (bn < 256) ? g_wlh : g_wrh;
    const int bnl = bn & 255;

    const int tid = threadIdx.x;
    const int wid = tid >> 5, lane = tid & 31;
    const int wm = wid >> 2, wn = wid & 3;
    const int g = lane >> 2, tg = lane & 3;

    float acc[4][4][4];
#pragma unroll
    for (int mt = 0; mt < 4; mt++)
#pragma unroll
        for (int nt = 0; nt < 4; nt++)
#pragma unroll
            for (int r = 0; r < 4; r++) acc[mt][nt][r] = 0.f;

    // A-chunk mapping: idx -> m = idx>>2, kc = (idx&3)*8   (512 chunks, 2/thread)
    // B-chunk mapping: idx -> k = idx>>4, nf = (idx&15)*8  (512 chunks, 2/thread)
    const int am0 = tid >> 2,          akc = (tid & 3) * 8;
    const int am1 = (tid + 256) >> 2;  // second chunk
    const int bk0 = tid >> 4,          bnf = (tid & 15) * 8;
    const int bk1 = (tid + 256) >> 4;

#define STAGE(slab, buf)                                                          \
    {                                                                             \
        int k0 = (slab) * 32;                                                     \
        cpa16(&As[buf][am0 * LDAH + akc],                                         \
              g_xh + (size_t)(bm + am0) * 128 + k0 + akc,                         \
              (bm + am0 < NN) ? 16 : 0);                                          \
        cpa16(&As[buf][am1 * LDAH + akc],                                         \
              g_xh + (size_t)(bm + am1) * 128 + k0 + akc,                         \
              (bm + am1 < NN) ? 16 : 0);                                          \
        cpa16(&Bs[buf][bk0 * LDBH + bnf],                                         \
              Bsrc + (size_t)(k0 + bk0) * 256 + bnl + bnf, 16);                   \
        cpa16(&Bs[buf][bk1 * LDBH + bnf],                                         \
              Bsrc + (size_t)(k0 + bk1) * 256 + bnl + bnf, 16);                   \
        asm volatile("cp.async.commit_group;");                                   \
    }

    STAGE(0, 0);

#pragma unroll
    for (int i = 0; i < 4; i++) {
        const int cur = i & 1;
        if (i < 3) STAGE(i + 1, cur ^ 1);
        if (i < 3) asm volatile("cp.async.wait_group 1;");
        else       asm volatile("cp.async.wait_group 0;");
        __syncthreads();

        const uint16_t* BsU = (const uint16_t*)Bs[cur];
#pragma unroll
        for (int ks = 0; ks < 2; ks++) {
            int kb = ks * 16;
            uint32_t a[4][4], b[4][2];
#pragma unroll
            for (int mt = 0; mt < 4; mt++) {
                int rb = wm * 64 + mt * 16 + g;
                a[mt][0] = *(const uint32_t*)(As[cur] + rb * LDAH + kb + 2 * tg);
                a[mt][1] = *(const uint32_t*)(As[cur] + (rb + 8) * LDAH + kb + 2 * tg);
                a[mt][2] = *(const uint32_t*)(As[cur] + rb * LDAH + kb + 2 * tg + 8);
                a[mt][3] = *(const uint32_t*)(As[cur] + (rb + 8) * LDAH + kb + 2 * tg + 8);
            }
#pragma unroll
            for (int nt = 0; nt < 4; nt++) {
                int cb = wn * 32 + nt * 8 + g;
                uint32_t lo0 = BsU[(kb + 2 * tg) * LDBH + cb];
                uint32_t hi0 = BsU[(kb + 2 * tg + 1) * LDBH + cb];
                uint32_t lo1 = BsU[(kb + 2 * tg + 8) * LDBH + cb];
                uint32_t hi1 = BsU[(kb + 2 * tg + 9) * LDBH + cb];
                b[nt][0] = lo0 | (hi0 << 16);
                b[nt][1] = lo1 | (hi1 << 16);
            }
#pragma unroll
            for (int mt = 0; mt < 4; mt++)
#pragma unroll
                for (int nt = 0; nt < 4; nt++)
                    mma_f16(acc[mt][nt], a[mt], b[nt]);
        }
        __syncthreads();
    }

    __half2* dst = (__half2*)((bn < 256) ? g_xl1h : g_xr1h);
#pragma unroll
    for (int mt = 0; mt < 4; mt++) {
        int row0 = bm + wm * 64 + mt * 16 + g;
#pragma unroll
        for (int nt = 0; nt < 4; nt++) {
            int col = bnl + wn * 32 + nt * 8 + 2 * tg;   // even
            if (row0 < NN)
                dst[((size_t)row0 * 256 + col) >> 1] =
                    __floats2half2_rn(acc[mt][nt][0], acc[mt][nt][1]);
            if (row0 + 8 < NN)
                dst[((size_t)(row0 + 8) * 256 + col) >> 1] =
                    __floats2half2_rn(acc[mt][nt][2], acc[mt][nt][3]);
        }
    }
}

// ---- layer-1 fused: score + online softmax + aggregate + b1 + ELU -----------
__global__ void k_fused1(const float* __restrict__ att1, const float* __restrict__ b1) {
    int t = threadIdx.x;
    int node = blockIdx.x * 8 + (t >> 5);
    if (node >= NN) return;
    int lane = t & 31, h = lane >> 2, q = lane & 3;
    int base = h * 32 + q * 8;
    int p0 = g_start[node], p1 = g_start[node + 1];

    float4 at0 = *(const float4*)(att1 + base);
    float4 at1 = *(const float4*)(att1 + base + 4);

    uint4 rr = *(const uint4*)(g_xr1h + (size_t)node * 256 + base);
    float2 xrA = __half22float2(*(__half2*)&rr.x);
    float2 xrB = __half22float2(*(__half2*)&rr.y);
    float2 xrC = __half22float2(*(__half2*)&rr.z);
    float2 xrD = __half22float2(*(__half2*)&rr.w);

    float m = -1e30f, den = 0.f;
    float acc[8];
#pragma unroll
    for (int i = 0; i < 8; i++) acc[i] = 0.f;

    for (int p = p0; p < p1; p++) {
        int s = g_csr_src[p];
        uint4 raw = *(const uint4*)(g_xl1h + (size_t)s * 256 + base);
        float2 lA = __half22float2(*(__half2*)&raw.x);
        float2 lB = __half22float2(*(__half2*)&raw.y);
        float2 lC = __half22float2(*(__half2*)&raw.z);
        float2 lD = __half22float2(*(__half2*)&raw.w);

        float v, sc = 0.f;
        v = lA.x + xrA.x; v = v > 0.f ? v : 0.2f * v; sc += at0.x * v;
        v = lA.y + xrA.y; v = v > 0.f ? v : 0.2f * v; sc += at0.y * v;
        v = lB.x + xrB.x; v = v > 0.f ? v : 0.2f * v; sc += at0.z * v;
        v = lB.y + xrB.y; v = v > 0.f ? v : 0.2f * v; sc += at0.w * v;
        v = lC.x + xrC.x; v = v > 0.f ? v : 0.2f * v; sc += at1.x * v;
        v = lC.y + xrC.y; v = v > 0.f ? v : 0.2f * v; sc += at1.y * v;
        v = lD.x + xrD.x; v = v > 0.f ? v : 0.2f * v; sc += at1.z * v;
        v = lD.y + xrD.y; v = v > 0.f ? v : 0.2f * v; sc += at1.w * v;
        sc += __shfl_xor_sync(0xFFFFFFFFu, sc, 1);
        sc += __shfl_xor_sync(0xFFFFFFFFu, sc, 2);

        if (sc <= m) {
            float w = __expf(sc - m);
            den += w;
            acc[0] += w * lA.x; acc[1] += w * lA.y; acc[2] += w * lB.x; acc[3] += w * lB.y;
            acc[4] += w * lC.x; acc[5] += w * lC.y; acc[6] += w * lD.x; acc[7] += w * lD.y;
        } else {
            float sfac = __expf(m - sc);
            den = den * sfac + 1.f;
            acc[0] = acc[0] * sfac + lA.x; acc[1] = acc[1] * sfac + lA.y;
            acc[2] = acc[2] * sfac + lB.x; acc[3] = acc[3] * sfac + lB.y;
            acc[4] = acc[4] * sfac + lC.x; acc[5] = acc[5] * sfac + lC.y;
            acc[6] = acc[6] * sfac + lD.x; acc[7] = acc[7] * sfac + lD.y;
            m = sc;
        }
    }

    float inv = 1.f / (den + 1e-16f);
    float4 bb0 = *(const float4*)(b1 + base);
    float4 bb1 = *(const float4*)(b1 + base + 4);
    float o[8];
    o[0] = acc[0] * inv + bb0.x; o[1] = acc[1] * inv + bb0.y;
    o[2] = acc[2] * inv + bb0.z; o[3] = acc[3] * inv + bb0.w;
    o[4] = acc[4] * inv + bb1.x; o[5] = acc[5] * inv + bb1.y;
    o[6] = acc[6] * inv + bb1.z; o[7] = acc[7] * inv + bb1.w;
#pragma unroll
    for (int i = 0; i < 8; i++) o[i] = o[i] > 0.f ? o[i] : expm1f(o[i]);

    uint4 packed;
    *(__half2*)&packed.x = __floats2half2_rn(o[0], o[1]);
    *(__half2*)&packed.y = __floats2half2_rn(o[2], o[3]);
    *(__half2*)&packed.z = __floats2half2_rn(o[4], o[5]);
    *(__half2*)&packed.w = __floats2half2_rn(o[6], o[7]);
    *(uint4*)(g_h1 + (size_t)node * 256 + base) = packed;
}

// ---------------- GEMM2: h[NN,256](fp16) @ [W2l | W2r][256,32] ---------------
__global__ void k_gemm2(const float* __restrict__ Wl, const float* __restrict__ Wr) {
    __shared__ float ws[256 * 32];
    __shared__ float hs[16][256];
    int tid = threadIdx.x;
    for (int i = tid; i < 256 * 32; i += 256) {
        int k = i >> 5, c = i & 31;
        ws[i] = (c < 16) ? Wl[k * 16 + c] : Wr[k * 16 + c - 16];
    }
    int node0 = blockIdx.x * 16;
    const __half2* hp = (const __half2*)g_h1;
    for (int i = tid; i < 16 * 128; i += 256) {
        int m = i >> 7, kk = (i & 127) * 2;
        int node = node0 + m;
        float2 v = make_float2(0.f, 0.f);
        if (node < NN) v = __half22float2(hp[((size_t)node * 256 + kk) >> 1]);
        hs[m][kk] = v.x;
        hs[m][kk + 1] = v.y;
    }
    __syncthreads();
    int c = tid & 31;
#pragma unroll
    for (int half = 0; half < 2; half++) {
        int m = (tid >> 5) + half * 8;
        int node = node0 + m;
        if (node < NN) {
            float sacc = 0.f;
#pragma unroll 8
            for (int k = 0; k < 256; k++) sacc += hs[m][k] * ws[k * 32 + c];
            if (c < 16) g_xl2[node * 16 + c] = sacc;
            else        g_xr2[node * 16 + c - 16] = sacc;
        }
    }
}

// ------- layer-2 fused: 2 nodes per warp (16 lanes each), online softmax -----
__global__ void k_fused2(const float* __restrict__ att2, const float* __restrict__ b2,
                         float* __restrict__ dout) {
    int t = threadIdx.x;
    int lane = t & 31;
    int half = lane >> 4, c = lane & 15;
    int node = blockIdx.x * 16 + (t >> 5) * 2 + half;   // NN % 16 == 0 -> always valid
    int p0 = g_start[node], p1 = g_start[node + 1];
    int deg = p1 - p0;
    int dego = __shfl_xor_sync(0xFFFFFFFFu, deg, 16);
    int nit = deg > dego ? deg : dego;

    float xr = g_xr2[node * 16 + c];
    float at = att2[c];
    float m = -1e30f, den = 0.f, acc = 0.f;

    for (int i = 0; i < nit; i++) {
        bool val = i < deg;
        int p = val ? (p0 + i) : p0;
        int s = g_csr_src[p];
        float xl = g_xl2[s * 16 + c];
        float v = xl + xr;
        v = v > 0.f ? v : 0.2f * v;
        float sc = v * at;
        sc += __shfl_xor_sync(0xFFFFFFFFu, sc, 8);
        sc += __shfl_xor_sync(0xFFFFFFFFu, sc, 4);
        sc += __shfl_xor_sync(0xFFFFFFFFu, sc, 2);
        sc += __shfl_xor_sync(0xFFFFFFFFu, sc, 1);
        if (!val) sc = -1e38f;
        if (sc <= m) {
            float w = __expf(sc - m);
            den += w;
            acc += w * xl;
        } else {
            float sfac = __expf(m - sc);
            den = den * sfac + 1.f;
            acc = acc * sfac + xl;
            m = sc;
        }
    }
    float v = acc / (den + 1e-16f) + b2[c];
    dout[node * 16 + c] = v >= 0.f ? v : 0.01f * v;
}

// ---------------- launch ------------------------------------------------------
extern "C" void kernel_launch(void* const* d_in, const int* in_sizes, int n_in,
                              void* d_out, int out_size) {
    const float* x    = (const float*)d_in[0];
    const int*   ei   = (const int*)d_in[1];
    const float* W1l  = (const float*)d_in[2];
    const float* W1r  = (const float*)d_in[3];
    const float* att1 = (const float*)d_in[4];
    const float* b1   = (const float*)d_in[5];
    const float* W2l  = (const float*)d_in[6];
    const float* W2r  = (const float*)d_in[7];
    const float* att2 = (const float*)d_in[8];
    const float* b2   = (const float*)d_in[9];
    float* out = (float*)d_out;

    k_init<<<(NN + 255) / 256, 256>>>();
    k_hist<<<(EE / 4 + 255) / 256, 256>>>(ei);
    k_cvt<<<(NX + 2 * NW + 255) / 256, 256>>>(x, W1l, W1r);
    k_scan<<<1, 1024>>>();
    k_scatter<<<(ET + 255) / 256, 256>>>(ei);

    dim3 g1(4, (NN + 127) / 128);
    k_gemm1<<<g1, 256>>>();

    k_fused1<<<(NN + 7) / 8, 256>>>(att1, b1);

    k_gemm2<<<(NN + 15) / 16, 256>>>(W2l, W2r);

    k_fused2<<<NN / 16, 256>>>(att2, b2, out);
}

// round 13
// speedup vs baseline: 1.3819x; 1.1430x over previous
#include <cuda_runtime.h>
#include <cuda_fp16.h>
#include <math.h>
#include <stdint.h>

#define NN 50000
#define EE 640000
#define ET 690000   // EE + NN self loops

// ---------------- scratch (device globals) ----------------------------------
__device__ __half g_xh[(size_t)NN * 128];      // X in fp16
__device__ __half g_wlh[128 * 256];            // W1l fp16
__device__ __half g_wrh[128 * 256];            // W1r fp16
__device__ __half g_xl1h[(size_t)NN * 256];
__device__ __half g_xr1h[(size_t)NN * 256];
__device__ __half g_h1[(size_t)NN * 256];      // layer-1 output (post-ELU), fp16
__device__ float  g_xl2[NN * 16];
__device__ float  g_xr2[NN * 16];
__device__ int    g_deg[NN];
__device__ int    g_start[NN + 1];
__device__ int    g_cursor[NN];
__device__ int    g_csr_src[ET];
__device__ int    g_bsum[64];
__device__ int    g_boff[64];

// ---------------- CSR construction ------------------------------------------
__global__ void k_init() {
    int i = blockIdx.x * 256 + threadIdx.x;
    if (i < NN) { g_deg[i] = 1; g_cursor[i] = 0; }   // deg=1: self loop pre-counted
}

__global__ void k_hist(const int* __restrict__ ei) {
    int e = (blockIdx.x * 256 + threadIdx.x) * 4;
    if (e + 4 <= EE) {
        int4 d = *(const int4*)(ei + EE + e);
        atomicAdd(&g_deg[d.x], 1);
        atomicAdd(&g_deg[d.y], 1);
        atomicAdd(&g_deg[d.z], 1);
        atomicAdd(&g_deg[d.w], 1);
    }
}

// ---- 3-phase multi-block scan ------------------------------------------------
// phase 1: 49 blocks x 1024 threads; per-block exclusive scan + block total
__global__ void k_scan1() {
    __shared__ int wsum[32];
    int b = blockIdx.x, t = threadIdx.x;
    int idx = b * 1024 + t;
    int v = (idx < NN) ? g_deg[idx] : 0;
    int lane = t & 31, w = t >> 5;
    int s = v;
#pragma unroll
    for (int o = 1; o < 32; o <<= 1) {
        int u = __shfl_up_sync(0xFFFFFFFFu, s, o);
        if (lane >= o) s += u;
    }
    if (lane == 31) wsum[w] = s;
    __syncthreads();
    if (w == 0) {
        int ws = wsum[lane];
        int ss = ws;
#pragma unroll
        for (int o = 1; o < 32; o <<= 1) {
            int u = __shfl_up_sync(0xFFFFFFFFu, ss, o);
            if (lane >= o) ss += u;
        }
        wsum[lane] = ss - ws;                 // exclusive warp offset
        if (lane == 31) g_bsum[b] = ss;       // block total
    }
    __syncthreads();
    if (idx < NN) g_start[idx] = (s - v) + wsum[w];
}

// phase 2: one warp scans the block totals (2 consecutive elems per lane)
__global__ void k_scan2() {
    int lane = threadIdx.x;                   // 32 threads
    int i0 = 2 * lane, i1 = 2 * lane + 1;
    int a = (i0 < 49) ? g_bsum[i0] : 0;
    int b = (i1 < 49) ? g_bsum[i1] : 0;
    int pair = a + b;
    int s = pair;
#pragma unroll
    for (int o = 1; o < 32; o <<= 1) {
        int u = __shfl_up_sync(0xFFFFFFFFu, s, o);
        if (lane >= o) s += u;
    }
    if (i0 < 64) g_boff[i0] = s - pair;       // exclusive offset for block i0
    if (i1 < 64) g_boff[i1] = s - b;          // exclusive offset for block i1
}

// phase 3: add block offsets
__global__ void k_scan3() {
    int idx = blockIdx.x * 256 + threadIdx.x;
    if (idx < NN) g_start[idx] += g_boff[idx >> 10];
    if (idx == NN) g_start[NN] = ET;
}

__global__ void k_scatter(const int* __restrict__ ei) {
    int e = blockIdx.x * 256 + threadIdx.x;
    if (e >= ET) return;
    int s = (e < EE) ? ei[e] : e - EE;
    int d = (e < EE) ? ei[EE + e] : e - EE;
    int p = g_start[d] + atomicAdd(&g_cursor[d], 1);
    g_csr_src[p] = s;
}

// ---------------- fp16 conversion of X, W1l, W1r -----------------------------
#define NX (NN * 128 / 8)          // 800000
#define NW (128 * 256 / 8)         // 4096
__global__ void k_cvt(const float* __restrict__ X,
                      const float* __restrict__ Wl,
                      const float* __restrict__ Wr) {
    int i = blockIdx.x * 256 + threadIdx.x;
    const float* src;
    __half* dst;
    int j;
    if (i < NX)              { src = X;  dst = g_xh;  j = i; }
    else if (i < NX + NW)    { src = Wl; dst = g_wlh; j = i - NX; }
    else if (i < NX + 2*NW)  { src = Wr; dst = g_wrh; j = i - NX - NW; }
    else return;
    float4 a = *(const float4*)(src + (size_t)j * 8);
    float4 b = *(const float4*)(src + (size_t)j * 8 + 4);
    uint4 o;
    *(__half2*)&o.x = __floats2half2_rn(a.x, a.y);
    *(__half2*)&o.y = __floats2half2_rn(a.z, a.w);
    *(__half2*)&o.z = __floats2half2_rn(b.x, b.y);
    *(__half2*)&o.w = __floats2half2_rn(b.z, b.w);
    *(uint4*)(dst + (size_t)j * 8) = o;
}

// ---------------- fp16 mma helper ---------------------------------------------
__device__ __forceinline__ void mma_f16(float c[4], const uint32_t a[4], const uint32_t b[2]) {
    asm volatile(
        "mma.sync.aligned.m16n8k16.row.col.f32.f16.f16.f32 "
        "{%0,%1,%2,%3},{%4,%5,%6,%7},{%8,%9},{%0,%1,%2,%3};"
        : "+f"(c[0]), "+f"(c[1]), "+f"(c[2]), "+f"(c[3])
        : "r"(a[0]), "r"(a[1]), "r"(a[2]), "r"(a[3]), "r"(b[0]), "r"(b[1]));
}

__device__ __forceinline__ void cpa16(void* smem_ptr, const void* gmem_ptr, int src_sz) {
    uint32_t saddr = (uint32_t)__cvta_generic_to_shared(smem_ptr);
    asm volatile("cp.async.cg.shared.global [%0], [%1], 16, %2;"
                 :: "r"(saddr), "l"(gmem_ptr), "r"(src_sz));
}

// ---------------- GEMM1 (fp16 TC, cp.async 2-stage, BK=32) -------------------
#define LDAH 40
#define LDBH 136
__global__ void __launch_bounds__(256, 2) k_gemm1() {
    __shared__ __half As[2][128 * LDAH];   // [m][k]
    __shared__ __half Bs[2][32 * LDBH];    // [k][n]
    const int bm = blockIdx.y * 128;
    const int bn = blockIdx.x * 128;
    const __half* Bsrc = (bn < 256) ? g_wlh : g_wrh;
    const int bnl = bn & 255;

    const int tid = threadIdx.x;
    const int wid = tid >> 5, lane = tid & 31;
    const int wm = wid >> 2, wn = wid & 3;
    const int g = lane >> 2, tg = lane & 3;

    float acc[4][4][4];
#pragma unroll
    for (int mt = 0; mt < 4; mt++)
#pragma unroll
        for (int nt = 0; nt < 4; nt++)
#pragma unroll
            for (int r = 0; r < 4; r++) acc[mt][nt][r] = 0.f;

    const int am0 = tid >> 2,          akc = (tid & 3) * 8;
    const int am1 = (tid + 256) >> 2;
    const int bk0 = tid >> 4,          bnf = (tid & 15) * 8;
    const int bk1 = (tid + 256) >> 4;

#define STAGE(slab, buf)                                                          \
    {                                                                             \
        int k0 = (slab) * 32;                                                     \
        cpa16(&As[buf][am0 * LDAH + akc],                                         \
              g_xh + (size_t)(bm + am0) * 128 + k0 + akc,                         \
              (bm + am0 < NN) ? 16 : 0);                                          \
        cpa16(&As[buf][am1 * LDAH + akc],                                         \
              g_xh + (size_t)(bm + am1) * 128 + k0 + akc,                         \
              (bm + am1 < NN) ? 16 : 0);                                          \
        cpa16(&Bs[buf][bk0 * LDBH + bnf],                                         \
              Bsrc + (size_t)(k0 + bk0) * 256 + bnl + bnf, 16);                   \
        cpa16(&Bs[buf][bk1 * LDBH + bnf],                                         \
              Bsrc + (size_t)(k0 + bk1) * 256 + bnl + bnf, 16);                   \
        asm volatile("cp.async.commit_group;");                                   \
    }

    STAGE(0, 0);

#pragma unroll
    for (int i = 0; i < 4; i++) {
        const int cur = i & 1;
        if (i < 3) STAGE(i + 1, cur ^ 1);
        if (i < 3) asm volatile("cp.async.wait_group 1;");
        else       asm volatile("cp.async.wait_group 0;");
        __syncthreads();

        const uint16_t* BsU = (const uint16_t*)Bs[cur];
#pragma unroll
        for (int ks = 0; ks < 2; ks++) {
            int kb = ks * 16;
            uint32_t a[4][4], b[4][2];
#pragma unroll
            for (int mt = 0; mt < 4; mt++) {
                int rb = wm * 64 + mt * 16 + g;
                a[mt][0] = *(const uint32_t*)(As[cur] + rb * LDAH + kb + 2 * tg);
                a[mt][1] = *(const uint32_t*)(As[cur] + (rb + 8) * LDAH + kb + 2 * tg);
                a[mt][2] = *(const uint32_t*)(As[cur] + rb * LDAH + kb + 2 * tg + 8);
                a[mt][3] = *(const uint32_t*)(As[cur] + (rb + 8) * LDAH + kb + 2 * tg + 8);
            }
#pragma unroll
            for (int nt = 0; nt < 4; nt++) {
                int cb = wn * 32 + nt * 8 + g;
                uint32_t lo0 = BsU[(kb + 2 * tg) * LDBH + cb];
                uint32_t hi0 = BsU[(kb + 2 * tg + 1) * LDBH + cb];
                uint32_t lo1 = BsU[(kb + 2 * tg + 8) * LDBH + cb];
                uint32_t hi1 = BsU[(kb + 2 * tg + 9) * LDBH + cb];
                b[nt][0] = lo0 | (hi0 << 16);
                b[nt][1] = lo1 | (hi1 << 16);
            }
#pragma unroll
            for (int mt = 0; mt < 4; mt++)
#pragma unroll
                for (int nt = 0; nt < 4; nt++)
                    mma_f16(acc[mt][nt], a[mt], b[nt]);
        }
        __syncthreads();
    }

    __half2* dst = (__half2*)((bn < 256) ? g_xl1h : g_xr1h);
#pragma unroll
    for (int mt = 0; mt < 4; mt++) {
        int row0 = bm + wm * 64 + mt * 16 + g;
#pragma unroll
        for (int nt = 0; nt < 4; nt++) {
            int col = bnl + wn * 32 + nt * 8 + 2 * tg;   // even
            if (row0 < NN)
                dst[((size_t)row0 * 256 + col) >> 1] =
                    __floats2half2_rn(acc[mt][nt][0], acc[mt][nt][1]);
            if (row0 + 8 < NN)
                dst[((size_t)(row0 + 8) * 256 + col) >> 1] =
                    __floats2half2_rn(acc[mt][nt][2], acc[mt][nt][3]);
        }
    }
}

// ---- layer-1 fused: score + online softmax + aggregate + b1 + ELU -----------
__global__ void k_fused1(const float* __restrict__ att1, const float* __restrict__ b1) {
    int t = threadIdx.x;
    int node = blockIdx.x * 8 + (t >> 5);
    if (node >= NN) return;
    int lane = t & 31, h = lane >> 2, q = lane & 3;
    int base = h * 32 + q * 8;
    int p0 = g_start[node], p1 = g_start[node + 1];

    float4 at0 = *(const float4*)(att1 + base);
    float4 at1 = *(const float4*)(att1 + base + 4);

    uint4 rr = *(const uint4*)(g_xr1h + (size_t)node * 256 + base);
    float2 xrA = __half22float2(*(__half2*)&rr.x);
    float2 xrB = __half22float2(*(__half2*)&rr.y);
    float2 xrC = __half22float2(*(__half2*)&rr.z);
    float2 xrD = __half22float2(*(__half2*)&rr.w);

    float m = -1e30f, den = 0.f;
    float acc[8];
#pragma unroll
    for (int i = 0; i < 8; i++) acc[i] = 0.f;

    for (int p = p0; p < p1; p++) {
        int s = g_csr_src[p];
        uint4 raw = *(const uint4*)(g_xl1h + (size_t)s * 256 + base);
        float2 lA = __half22float2(*(__half2*)&raw.x);
        float2 lB = __half22float2(*(__half2*)&raw.y);
        float2 lC = __half22float2(*(__half2*)&raw.z);
        float2 lD = __half22float2(*(__half2*)&raw.w);

        float v, sc = 0.f;
        v = lA.x + xrA.x; v = v > 0.f ? v : 0.2f * v; sc += at0.x * v;
        v = lA.y + xrA.y; v = v > 0.f ? v : 0.2f * v; sc += at0.y * v;
        v = lB.x + xrB.x; v = v > 0.f ? v : 0.2f * v; sc += at0.z * v;
        v = lB.y + xrB.y; v = v > 0.f ? v : 0.2f * v; sc += at0.w * v;
        v = lC.x + xrC.x; v = v > 0.f ? v : 0.2f * v; sc += at1.x * v;
        v = lC.y + xrC.y; v = v > 0.f ? v : 0.2f * v; sc += at1.y * v;
        v = lD.x + xrD.x; v = v > 0.f ? v : 0.2f * v; sc += at1.z * v;
        v = lD.y + xrD.y; v = v > 0.f ? v : 0.2f * v; sc += at1.w * v;
        sc += __shfl_xor_sync(0xFFFFFFFFu, sc, 1);
        sc += __shfl_xor_sync(0xFFFFFFFFu, sc, 2);

        if (sc <= m) {
            float w = __expf(sc - m);
            den += w;
            acc[0] += w * lA.x; acc[1] += w * lA.y; acc[2] += w * lB.x; acc[3] += w * lB.y;
            acc[4] += w * lC.x; acc[5] += w * lC.y; acc[6] += w * lD.x; acc[7] += w * lD.y;
        } else {
            float sfac = __expf(m - sc);
            den = den * sfac + 1.f;
            acc[0] = acc[0] * sfac + lA.x; acc[1] = acc[1] * sfac + lA.y;
            acc[2] = acc[2] * sfac + lB.x; acc[3] = acc[3] * sfac + lB.y;
            acc[4] = acc[4] * sfac + lC.x; acc[5] = acc[5] * sfac + lC.y;
            acc[6] = acc[6] * sfac + lD.x; acc[7] = acc[7] * sfac + lD.y;
            m = sc;
        }
    }

    float inv = 1.f / (den + 1e-16f);
    float4 bb0 = *(const float4*)(b1 + base);
    float4 bb1 = *(const float4*)(b1 + base + 4);
    float o[8];
    o[0] = acc[0] * inv + bb0.x; o[1] = acc[1] * inv + bb0.y;
    o[2] = acc[2] * inv + bb0.z; o[3] = acc[3] * inv + bb0.w;
    o[4] = acc[4] * inv + bb1.x; o[5] = acc[5] * inv + bb1.y;
    o[6] = acc[6] * inv + bb1.z; o[7] = acc[7] * inv + bb1.w;
#pragma unroll
    for (int i = 0; i < 8; i++) o[i] = o[i] > 0.f ? o[i] : expm1f(o[i]);

    uint4 packed;
    *(__half2*)&packed.x = __floats2half2_rn(o[0], o[1]);
    *(__half2*)&packed.y = __floats2half2_rn(o[2], o[3]);
    *(__half2*)&packed.z = __floats2half2_rn(o[4], o[5]);
    *(__half2*)&packed.w = __floats2half2_rn(o[6], o[7]);
    *(uint4*)(g_h1 + (size_t)node * 256 + base) = packed;
}

// ---------------- GEMM2: h[NN,256](fp16) @ [W2l | W2r][256,32] ---------------
__global__ void k_gemm2(const float* __restrict__ Wl, const float* __restrict__ Wr) {
    __shared__ float ws[256 * 32];
    __shared__ float hs[16][256];
    int tid = threadIdx.x;
    for (int i = tid; i < 256 * 32; i += 256) {
        int k = i >> 5, c = i & 31;
        ws[i] = (c < 16) ? Wl[k * 16 + c] : Wr[k * 16 + c - 16];
    }
    int node0 = blockIdx.x * 16;
    const __half2* hp = (const __half2*)g_h1;
    for (int i = tid; i < 16 * 128; i += 256) {
        int m = i >> 7, kk = (i & 127) * 2;
        int node = node0 + m;
        float2 v = make_float2(0.f, 0.f);
        if (node < NN) v = __half22float2(hp[((size_t)node * 256 + kk) >> 1]);
        hs[m][kk] = v.x;
        hs[m][kk + 1] = v.y;
    }
    __syncthreads();
    int c = tid & 31;
#pragma unroll
    for (int half = 0; half < 2; half++) {
        int m = (tid >> 5) + half * 8;
        int node = node0 + m;
        if (node < NN) {
            float sacc = 0.f;
#pragma unroll 8
            for (int k = 0; k < 256; k++) sacc += hs[m][k] * ws[k * 32 + c];
            if (c < 16) g_xl2[node * 16 + c] = sacc;
            else        g_xr2[node * 16 + c - 16] = sacc;
        }
    }
}

// ------- layer-2 fused: 2 nodes per warp (16 lanes each), online softmax -----
__global__ void k_fused2(const float* __restrict__ att2, const float* __restrict__ b2,
                         float* __restrict__ dout) {
    int t = threadIdx.x;
    int lane = t & 31;
    int half = lane >> 4, c = lane & 15;
    int node = blockIdx.x * 16 + (t >> 5) * 2 + half;   // NN % 16 == 0 -> always valid
    int p0 = g_start[node], p1 = g_start[node + 1];
    int deg = p1 - p0;
    int dego = __shfl_xor_sync(0xFFFFFFFFu, deg, 16);
    int nit = deg > dego ? deg : dego;

    float xr = g_xr2[node * 16 + c];
    float at = att2[c];
    float m = -1e30f, den = 0.f, acc = 0.f;

    for (int i = 0; i < nit; i++) {
        bool val = i < deg;
        int p = val ? (p0 + i) : p0;
        int s = g_csr_src[p];
        float xl = g_xl2[s * 16 + c];
        float v = xl + xr;
        v = v > 0.f ? v : 0.2f * v;
        float sc = v * at;
        sc += __shfl_xor_sync(0xFFFFFFFFu, sc, 8);
        sc += __shfl_xor_sync(0xFFFFFFFFu, sc, 4);
        sc += __shfl_xor_sync(0xFFFFFFFFu, sc, 2);
        sc += __shfl_xor_sync(0xFFFFFFFFu, sc, 1);
        if (!val) sc = -1e38f;
        if (sc <= m) {
            float w = __expf(sc - m);
            den += w;
            acc += w * xl;
        } else {
            float sfac = __expf(m - sc);
            den = den * sfac + 1.f;
            acc = acc * sfac + xl;
            m = sc;
        }
    }
    float v = acc / (den + 1e-16f) + b2[c];
    dout[node * 16 + c] = v >= 0.f ? v : 0.01f * v;
}

// ---------------- launch ------------------------------------------------------
extern "C" void kernel_launch(void* const* d_in, const int* in_sizes, int n_in,
                              void* d_out, int out_size) {
    const float* x    = (const float*)d_in[0];
    const int*   ei   = (const int*)d_in[1];
    const float* W1l  = (const float*)d_in[2];
    const float* W1r  = (const float*)d_in[3];
    const float* att1 = (const float*)d_in[4];
    const float* b1   = (const float*)d_in[5];
    const float* W2l  = (const float*)d_in[6];
    const float* W2r  = (const float*)d_in[7];
    const float* att2 = (const float*)d_in[8];
    const float* b2   = (const float*)d_in[9];
    float* out = (float*)d_out;

    k_init<<<(NN + 255) / 256, 256>>>();
    k_hist<<<(EE / 4 + 255) / 256, 256>>>(ei);
    k_cvt<<<(NX + 2 * NW + 255) / 256, 256>>>(x, W1l, W1r);
    k_scan1<<<49, 1024>>>();
    k_scan2<<<1, 32>>>();
    k_scan3<<<(NN + 256) / 256, 256>>>();
    k_scatter<<<(ET + 255) / 256, 256>>>(ei);

    dim3 g1(4, (NN + 127) / 128);
    k_gemm1<<<g1, 256>>>();

    k_fused1<<<(NN + 7) / 8, 256>>>(att1, b1);

    k_gemm2<<<(NN + 15) / 16, 256>>>(W2l, W2r);

    k_fused2<<<NN / 16, 256>>>(att2, b2, out);
}

// round 14
// speedup vs baseline: 1.4273x; 1.0328x over previous
#include <cuda_runtime.h>
#include <cuda_fp16.h>
#include <math.h>
#include <stdint.h>

#define NN 50000
#define EE 640000
#define ET 690000   // EE + NN self loops

// ---------------- scratch (device globals) ----------------------------------
__device__ __half g_xh[(size_t)NN * 128];      // X in fp16
__device__ __half g_wlh[128 * 256];            // W1l fp16
__device__ __half g_wrh[128 * 256];            // W1r fp16
__device__ __half g_xl1h[(size_t)NN * 256];
__device__ __half g_xr1h[(size_t)NN * 256];
__device__ __half g_h1[(size_t)NN * 256];      // layer-1 output (post-ELU), fp16
__device__ float  g_xl2[NN * 16];
__device__ float  g_xr2[NN * 16];
__device__ int    g_deg[NN];
__device__ int    g_start[NN + 1];
__device__ int    g_cursor[NN];
__device__ int    g_csr_src[ET];
__device__ int    g_bsum[64];
__device__ int    g_boff[64];

// ---------------- CSR construction ------------------------------------------
__global__ void k_init() {
    int i = blockIdx.x * 256 + threadIdx.x;
    if (i < NN) { g_deg[i] = 1; g_cursor[i] = 0; }   // deg=1: self loop pre-counted
}

__global__ void k_hist(const int* __restrict__ ei) {
    int e = (blockIdx.x * 256 + threadIdx.x) * 4;
    if (e + 4 <= EE) {
        int4 d = *(const int4*)(ei + EE + e);
        atomicAdd(&g_deg[d.x], 1);
        atomicAdd(&g_deg[d.y], 1);
        atomicAdd(&g_deg[d.z], 1);
        atomicAdd(&g_deg[d.w], 1);
    }
}

// ---- 3-phase multi-block scan ------------------------------------------------
__global__ void k_scan1() {
    __shared__ int wsum[32];
    int b = blockIdx.x, t = threadIdx.x;
    int idx = b * 1024 + t;
    int v = (idx < NN) ? g_deg[idx] : 0;
    int lane = t & 31, w = t >> 5;
    int s = v;
#pragma unroll
    for (int o = 1; o < 32; o <<= 1) {
        int u = __shfl_up_sync(0xFFFFFFFFu, s, o);
        if (lane >= o) s += u;
    }
    if (lane == 31) wsum[w] = s;
    __syncthreads();
    if (w == 0) {
        int ws = wsum[lane];
        int ss = ws;
#pragma unroll
        for (int o = 1; o < 32; o <<= 1) {
            int u = __shfl_up_sync(0xFFFFFFFFu, ss, o);
            if (lane >= o) ss += u;
        }
        wsum[lane] = ss - ws;                 // exclusive warp offset
        if (lane == 31) g_bsum[b] = ss;       // block total
    }
    __syncthreads();
    if (idx < NN) g_start[idx] = (s - v) + wsum[w];
}

__global__ void k_scan2() {
    int lane = threadIdx.x;                   // 32 threads
    int i0 = 2 * lane, i1 = 2 * lane + 1;
    int a = (i0 < 49) ? g_bsum[i0] : 0;
    int b = (i1 < 49) ? g_bsum[i1] : 0;
    int pair = a + b;
    int s = pair;
#pragma unroll
    for (int o = 1; o < 32; o <<= 1) {
        int u = __shfl_up_sync(0xFFFFFFFFu, s, o);
        if (lane >= o) s += u;
    }
    if (i0 < 64) g_boff[i0] = s - pair;
    if (i1 < 64) g_boff[i1] = s - b;
}

__global__ void k_scan3() {
    int idx = blockIdx.x * 256 + threadIdx.x;
    if (idx < NN) g_start[idx] += g_boff[idx >> 10];
    if (idx == NN) g_start[NN] = ET;
}

__global__ void k_scatter(const int* __restrict__ ei) {
    int e = blockIdx.x * 256 + threadIdx.x;
    if (e >= ET) return;
    int s = (e < EE) ? ei[e] : e - EE;
    int d = (e < EE) ? ei[EE + e] : e - EE;
    int p = g_start[d] + atomicAdd(&g_cursor[d], 1);
    g_csr_src[p] = s;
}

// ---------------- fp16 conversion of X, W1l, W1r -----------------------------
#define NX (NN * 128 / 8)          // 800000
#define NW (128 * 256 / 8)         // 4096
__global__ void k_cvt(const float* __restrict__ X,
                      const float* __restrict__ Wl,
                      const float* __restrict__ Wr) {
    int i = blockIdx.x * 256 + threadIdx.x;
    const float* src;
    __half* dst;
    int j;
    if (i < NX)              { src = X;  dst = g_xh;  j = i; }
    else if (i < NX + NW)    { src = Wl; dst = g_wlh; j = i - NX; }
    else if (i < NX + 2*NW)  { src = Wr; dst = g_wrh; j = i - NX - NW; }
    else return;
    float4 a = *(const float4*)(src + (size_t)j * 8);
    float4 b = *(const float4*)(src + (size_t)j * 8 + 4);
    uint4 o;
    *(__half2*)&o.x = __floats2half2_rn(a.x, a.y);
    *(__half2*)&o.y = __floats2half2_rn(a.z, a.w);
    *(__half2*)&o.z = __floats2half2_rn(b.x, b.y);
    *(__half2*)&o.w = __floats2half2_rn(b.z, b.w);
    *(uint4*)(dst + (size_t)j * 8) = o;
}

// ---------------- fp16 mma helper ---------------------------------------------
__device__ __forceinline__ void mma_f16(float c[4], const uint32_t a[4], const uint32_t b[2]) {
    asm volatile(
        "mma.sync.aligned.m16n8k16.row.col.f32.f16.f16.f32 "
        "{%0,%1,%2,%3},{%4,%5,%6,%7},{%8,%9},{%0,%1,%2,%3};"
        : "+f"(c[0]), "+f"(c[1]), "+f"(c[2]), "+f"(c[3])
        : "r"(a[0]), "r"(a[1]), "r"(a[2]), "r"(a[3]), "r"(b[0]), "r"(b[1]));
}

__device__ __forceinline__ void cpa16(void* smem_ptr, const void* gmem_ptr, int src_sz) {
    uint32_t saddr = (uint32_t)__cvta_generic_to_shared(smem_ptr);
    asm volatile("cp.async.cg.shared.global [%0], [%1], 16, %2;"
                 :: "r"(saddr), "l"(gmem_ptr), "r"(src_sz));
}

// ---------------- GEMM1 (fp16 TC, cp.async 2-stage, BK=32) -------------------
#define LDAH 40
#define LDBH 136
__global__ void __launch_bounds__(256, 2) k_gemm1() {
    __shared__ __half As[2][128 * LDAH];   // [m][k]
    __shared__ __half Bs[2][32 * LDBH];    // [k][n]
    const int bm = blockIdx.y * 128;
    const int bn = blockIdx.x * 128;
    const __half* Bsrc = (bn < 256) ? g_wlh : g_wrh;
    const int bnl = bn & 255;

    const int tid = threadIdx.x;
    const int wid = tid >> 5, lane = tid & 31;
    const int wm = wid >> 2, wn = wid & 3;
    const int g = lane >> 2, tg = lane & 3;

    float acc[4][4][4];
#pragma unroll
    for (int mt = 0; mt < 4; mt++)
#pragma unroll
        for (int nt = 0; nt < 4; nt++)
#pragma unroll
            for (int r = 0; r < 4; r++) acc[mt][nt][r] = 0.f;

    const int am0 = tid >> 2,          akc = (tid & 3) * 8;
    const int am1 = (tid + 256) >> 2;
    const int bk0 = tid >> 4,          bnf = (tid & 15) * 8;
    const int bk1 = (tid + 256) >> 4;

#define STAGE(slab, buf)                                                          \
    {                                                                             \
        int k0 = (slab) * 32;                                                     \
        cpa16(&As[buf][am0 * LDAH + akc],                                         \
              g_xh + (size_t)(bm + am0) * 128 + k0 + akc,                         \
              (bm + am0 < NN) ? 16 : 0);                                          \
        cpa16(&As[buf][am1 * LDAH + akc],                                         \
              g_xh + (size_t)(bm + am1) * 128 + k0 + akc,                         \
              (bm + am1 < NN) ? 16 : 0);                                          \
        cpa16(&Bs[buf][bk0 * LDBH + bnf],                                         \
              Bsrc + (size_t)(k0 + bk0) * 256 + bnl + bnf, 16);                   \
        cpa16(&Bs[buf][bk1 * LDBH + bnf],                                         \
              Bsrc + (size_t)(k0 + bk1) * 256 + bnl + bnf, 16);                   \
        asm volatile("cp.async.commit_group;");                                   \
    }

    STAGE(0, 0);

#pragma unroll
    for (int i = 0; i < 4; i++) {
        const int cur = i & 1;
        if (i < 3) STAGE(i + 1, cur ^ 1);
        if (i < 3) asm volatile("cp.async.wait_group 1;");
        else       asm volatile("cp.async.wait_group 0;");
        __syncthreads();

        const uint16_t* BsU = (const uint16_t*)Bs[cur];
#pragma unroll
        for (int ks = 0; ks < 2; ks++) {
            int kb = ks * 16;
            uint32_t a[4][4], b[4][2];
#pragma unroll
            for (int mt = 0; mt < 4; mt++) {
                int rb = wm * 64 + mt * 16 + g;
                a[mt][0] = *(const uint32_t*)(As[cur] + rb * LDAH + kb + 2 * tg);
                a[mt][1] = *(const uint32_t*)(As[cur] + (rb + 8) * LDAH + kb + 2 * tg);
                a[mt][2] = *(const uint32_t*)(As[cur] + rb * LDAH + kb + 2 * tg + 8);
                a[mt][3] = *(const uint32_t*)(As[cur] + (rb + 8) * LDAH + kb + 2 * tg + 8);
            }
#pragma unroll
            for (int nt = 0; nt < 4; nt++) {
                int cb = wn * 32 + nt * 8 + g;
                uint32_t lo0 = BsU[(kb + 2 * tg) * LDBH + cb];
                uint32_t hi0 = BsU[(kb + 2 * tg + 1) * LDBH + cb];
                uint32_t lo1 = BsU[(kb + 2 * tg + 8) * LDBH + cb];
                uint32_t hi1 = BsU[(kb + 2 * tg + 9) * LDBH + cb];
                b[nt][0] = lo0 | (hi0 << 16);
                b[nt][1] = lo1 | (hi1 << 16);
            }
#pragma unroll
            for (int mt = 0; mt < 4; mt++)
#pragma unroll
                for (int nt = 0; nt < 4; nt++)
                    mma_f16(acc[mt][nt], a[mt], b[nt]);
        }
        __syncthreads();
    }

    __half2* dst = (__half2*)((bn < 256) ? g_xl1h : g_xr1h);
#pragma unroll
    for (int mt = 0; mt < 4; mt++) {
        int row0 = bm + wm * 64 + mt * 16 + g;
#pragma unroll
        for (int nt = 0; nt < 4; nt++) {
            int col = bnl + wn * 32 + nt * 8 + 2 * tg;   // even
            if (row0 < NN)
                dst[((size_t)row0 * 256 + col) >> 1] =
                    __floats2half2_rn(acc[mt][nt][0], acc[mt][nt][1]);
            if (row0 + 8 < NN)
                dst[((size_t)(row0 + 8) * 256 + col) >> 1] =
                    __floats2half2_rn(acc[mt][nt][2], acc[mt][nt][3]);
        }
    }
}

// ---- layer-1 fused: score + online softmax + aggregate + b1 + ELU -----------
__global__ void k_fused1(const float* __restrict__ att1, const float* __restrict__ b1) {
    int t = threadIdx.x;
    int node = blockIdx.x * 8 + (t >> 5);
    if (node >= NN) return;
    int lane = t & 31, h = lane >> 2, q = lane & 3;
    int base = h * 32 + q * 8;
    int p0 = g_start[node], p1 = g_start[node + 1];

    float4 at0 = *(const float4*)(att1 + base);
    float4 at1 = *(const float4*)(att1 + base + 4);

    uint4 rr = *(const uint4*)(g_xr1h + (size_t)node * 256 + base);
    float2 xrA = __half22float2(*(__half2*)&rr.x);
    float2 xrB = __half22float2(*(__half2*)&rr.y);
    float2 xrC = __half22float2(*(__half2*)&rr.z);
    float2 xrD = __half22float2(*(__half2*)&rr.w);

    float m = -1e30f, den = 0.f;
    float acc[8];
#pragma unroll
    for (int i = 0; i < 8; i++) acc[i] = 0.f;

    for (int p = p0; p < p1; p++) {
        int s = g_csr_src[p];
        uint4 raw = *(const uint4*)(g_xl1h + (size_t)s * 256 + base);
        float2 lA = __half22float2(*(__half2*)&raw.x);
        float2 lB = __half22float2(*(__half2*)&raw.y);
        float2 lC = __half22float2(*(__half2*)&raw.z);
        float2 lD = __half22float2(*(__half2*)&raw.w);

        float v, sc = 0.f;
        v = lA.x + xrA.x; v = v > 0.f ? v : 0.2f * v; sc += at0.x * v;
        v = lA.y + xrA.y; v = v > 0.f ? v : 0.2f * v; sc += at0.y * v;
        v = lB.x + xrB.x; v = v > 0.f ? v : 0.2f * v; sc += at0.z * v;
        v = lB.y + xrB.y; v = v > 0.f ? v : 0.2f * v; sc += at0.w * v;
        v = lC.x + xrC.x; v = v > 0.f ? v : 0.2f * v; sc += at1.x * v;
        v = lC.y + xrC.y; v = v > 0.f ? v : 0.2f * v; sc += at1.y * v;
        v = lD.x + xrD.x; v = v > 0.f ? v : 0.2f * v; sc += at1.z * v;
        v = lD.y + xrD.y; v = v > 0.f ? v : 0.2f * v; sc += at1.w * v;
        sc += __shfl_xor_sync(0xFFFFFFFFu, sc, 1);
        sc += __shfl_xor_sync(0xFFFFFFFFu, sc, 2);

        if (sc <= m) {
            float w = __expf(sc - m);
            den += w;
            acc[0] += w * lA.x; acc[1] += w * lA.y; acc[2] += w * lB.x; acc[3] += w * lB.y;
            acc[4] += w * lC.x; acc[5] += w * lC.y; acc[6] += w * lD.x; acc[7] += w * lD.y;
        } else {
            float sfac = __expf(m - sc);
            den = den * sfac + 1.f;
            acc[0] = acc[0] * sfac + lA.x; acc[1] = acc[1] * sfac + lA.y;
            acc[2] = acc[2] * sfac + lB.x; acc[3] = acc[3] * sfac + lB.y;
            acc[4] = acc[4] * sfac + lC.x; acc[5] = acc[5] * sfac + lC.y;
            acc[6] = acc[6] * sfac + lD.x; acc[7] = acc[7] * sfac + lD.y;
            m = sc;
        }
    }

    float inv = 1.f / (den + 1e-16f);
    float4 bb0 = *(const float4*)(b1 + base);
    float4 bb1 = *(const float4*)(b1 + base + 4);
    float o[8];
    o[0] = acc[0] * inv + bb0.x; o[1] = acc[1] * inv + bb0.y;
    o[2] = acc[2] * inv + bb0.z; o[3] = acc[3] * inv + bb0.w;
    o[4] = acc[4] * inv + bb1.x; o[5] = acc[5] * inv + bb1.y;
    o[6] = acc[6] * inv + bb1.z; o[7] = acc[7] * inv + bb1.w;
#pragma unroll
    for (int i = 0; i < 8; i++) o[i] = o[i] > 0.f ? o[i] : expm1f(o[i]);

    uint4 packed;
    *(__half2*)&packed.x = __floats2half2_rn(o[0], o[1]);
    *(__half2*)&packed.y = __floats2half2_rn(o[2], o[3]);
    *(__half2*)&packed.z = __floats2half2_rn(o[4], o[5]);
    *(__half2*)&packed.w = __floats2half2_rn(o[6], o[7]);
    *(uint4*)(g_h1 + (size_t)node * 256 + base) = packed;
}

// ---------------- GEMM2: h[NN,256](fp16) @ [W2l | W2r][256,32] ---------------
__global__ void k_gemm2(const float* __restrict__ Wl, const float* __restrict__ Wr) {
    __shared__ float ws[256 * 32];
    __shared__ float hs[16][256];
    int tid = threadIdx.x;
    for (int i = tid; i < 256 * 32; i += 256) {
        int k = i >> 5, c = i & 31;
        ws[i] = (c < 16) ? Wl[k * 16 + c] : Wr[k * 16 + c - 16];
    }
    int node0 = blockIdx.x * 16;
    const __half2* hp = (const __half2*)g_h1;
    for (int i = tid; i < 16 * 128; i += 256) {
        int m = i >> 7, kk = (i & 127) * 2;
        int node = node0 + m;
        float2 v = make_float2(0.f, 0.f);
        if (node < NN) v = __half22float2(hp[((size_t)node * 256 + kk) >> 1]);
        hs[m][kk] = v.x;
        hs[m][kk + 1] = v.y;
    }
    __syncthreads();
    int c = tid & 31;
#pragma unroll
    for (int half = 0; half < 2; half++) {
        int m = (tid >> 5) + half * 8;
        int node = node0 + m;
        if (node < NN) {
            float sacc = 0.f;
#pragma unroll 8
            for (int k = 0; k < 256; k++) sacc += hs[m][k] * ws[k * 32 + c];
            if (c < 16) g_xl2[node * 16 + c] = sacc;
            else        g_xr2[node * 16 + c - 16] = sacc;
        }
    }
}

// ------- layer-2 fused: 2 nodes per warp (16 lanes each), online softmax -----
__global__ void k_fused2(const float* __restrict__ att2, const float* __restrict__ b2,
                         float* __restrict__ dout) {
    int t = threadIdx.x;
    int lane = t & 31;
    int half = lane >> 4, c = lane & 15;
    int node = blockIdx.x * 16 + (t >> 5) * 2 + half;   // NN % 16 == 0 -> always valid
    int p0 = g_start[node], p1 = g_start[node + 1];
    int deg = p1 - p0;
    int dego = __shfl_xor_sync(0xFFFFFFFFu, deg, 16);
    int nit = deg > dego ? deg : dego;

    float xr = g_xr2[node * 16 + c];
    float at = att2[c];
    float m = -1e30f, den = 0.f, acc = 0.f;

    for (int i = 0; i < nit; i++) {
        bool val = i < deg;
        int p = val ? (p0 + i) : p0;
        int s = g_csr_src[p];
        float xl = g_xl2[s * 16 + c];
        float v = xl + xr;
        v = v > 0.f ? v : 0.2f * v;
        float sc = v * at;
        sc += __shfl_xor_sync(0xFFFFFFFFu, sc, 8);
        sc += __shfl_xor_sync(0xFFFFFFFFu, sc, 4);
        sc += __shfl_xor_sync(0xFFFFFFFFu, sc, 2);
        sc += __shfl_xor_sync(0xFFFFFFFFu, sc, 1);
        if (!val) sc = -1e38f;
        if (sc <= m) {
            float w = __expf(sc - m);
            den += w;
            acc += w * xl;
        } else {
            float sfac = __expf(m - sc);
            den = den * sfac + 1.f;
            acc = acc * sfac + xl;
            m = sc;
        }
    }
    float v = acc / (den + 1e-16f) + b2[c];
    dout[node * 16 + c] = v >= 0.f ? v : 0.01f * v;
}

// ---------------- launch ------------------------------------------------------
extern "C" void kernel_launch(void* const* d_in, const int* in_sizes, int n_in,
                              void* d_out, int out_size) {
    const float* x    = (const float*)d_in[0];
    const int*   ei   = (const int*)d_in[1];
    const float* W1l  = (const float*)d_in[2];
    const float* W1r  = (const float*)d_in[3];
    const float* att1 = (const float*)d_in[4];
    const float* b1   = (const float*)d_in[5];
    const float* W2l  = (const float*)d_in[6];
    const float* W2r  = (const float*)d_in[7];
    const float* att2 = (const float*)d_in[8];
    const float* b2   = (const float*)d_in[9];
    float* out = (float*)d_out;

    // one-time host-object creation (no device memory)
    static cudaStream_t s2 = nullptr;
    static cudaEvent_t evFork = nullptr, evJoin = nullptr;
    if (s2 == nullptr) {
        cudaStreamCreateWithFlags(&s2, cudaStreamNonBlocking);
        cudaEventCreateWithFlags(&evFork, cudaEventDisableTiming);
        cudaEventCreateWithFlags(&evJoin, cudaEventDisableTiming);
    }

    // fork: CSR chain on s2, cvt+gemm1 on main stream
    cudaEventRecord(evFork, 0);
    cudaStreamWaitEvent(s2, evFork, 0);

    k_init<<<(NN + 255) / 256, 256, 0, s2>>>();
    k_hist<<<(EE / 4 + 255) / 256, 256, 0, s2>>>(ei);
    k_scan1<<<49, 1024, 0, s2>>>();
    k_scan2<<<1, 32, 0, s2>>>();
    k_scan3<<<(NN + 256) / 256, 256, 0, s2>>>();
    k_scatter<<<(ET + 255) / 256, 256, 0, s2>>>(ei);
    cudaEventRecord(evJoin, s2);

    k_cvt<<<(NX + 2 * NW + 255) / 256, 256>>>(x, W1l, W1r);
    dim3 g1(4, (NN + 127) / 128);
    k_gemm1<<<g1, 256>>>();

    // join: fused1 needs both CSR and gemm1 results
    cudaStreamWaitEvent(0, evJoin, 0);

    k_fused1<<<(NN + 7) / 8, 256>>>(att1, b1);

    k_gemm2<<<(NN + 15) / 16, 256>>>(W2l, W2r);

    k_fused2<<<NN / 16, 256>>>(att2, b2, out);
}

// round 15
// speedup vs baseline: 1.4546x; 1.0192x over previous
#include <cuda_runtime.h>
#include <cuda_fp16.h>
#include <math.h>
#include <stdint.h>

#define NN 50000
#define EE 640000
#define ET 690000   // EE + NN self loops

// ---------------- scratch (device globals) ----------------------------------
__device__ __half g_xh[(size_t)NN * 128];      // X in fp16
__device__ __half g_wlh[128 * 256];            // W1l fp16
__device__ __half g_wrh[128 * 256];            // W1r fp16
__device__ __half g_xl1h[(size_t)NN * 256];
__device__ __half g_xr1h[(size_t)NN * 256];
__device__ __half g_h1[(size_t)NN * 256];      // layer-1 output (post-ELU), fp16
__device__ float  g_xl2[NN * 16];
__device__ float  g_xr2[NN * 16];
__device__ int    g_deg[NN];
__device__ int    g_start[NN + 1];
__device__ int    g_cursor[NN];
__device__ int    g_csr_src[ET];
__device__ int    g_bsum[64];
__device__ int    g_boff[64];

// ---------------- CSR construction ------------------------------------------
__global__ void k_init() {
    int i = blockIdx.x * 256 + threadIdx.x;
    if (i < NN) { g_deg[i] = 1; g_cursor[i] = 0; }   // deg=1: self loop pre-counted
}

__global__ void k_hist(const int* __restrict__ ei) {
    int e = (blockIdx.x * 256 + threadIdx.x) * 4;
    if (e + 4 <= EE) {
        int4 d = *(const int4*)(ei + EE + e);
        atomicAdd(&g_deg[d.x], 1);
        atomicAdd(&g_deg[d.y], 1);
        atomicAdd(&g_deg[d.z], 1);
        atomicAdd(&g_deg[d.w], 1);
    }
}

// ---- 3-phase multi-block scan ------------------------------------------------
__global__ void k_scan1() {
    __shared__ int wsum[32];
    int b = blockIdx.x, t = threadIdx.x;
    int idx = b * 1024 + t;
    int v = (idx < NN) ? g_deg[idx] : 0;
    int lane = t & 31, w = t >> 5;
    int s = v;
#pragma unroll
    for (int o = 1; o < 32; o <<= 1) {
        int u = __shfl_up_sync(0xFFFFFFFFu, s, o);
        if (lane >= o) s += u;
    }
    if (lane == 31) wsum[w] = s;
    __syncthreads();
    if (w == 0) {
        int ws = wsum[lane];
        int ss = ws;
#pragma unroll
        for (int o = 1; o < 32; o <<= 1) {
            int u = __shfl_up_sync(0xFFFFFFFFu, ss, o);
            if (lane >= o) ss += u;
        }
        wsum[lane] = ss - ws;                 // exclusive warp offset
        if (lane == 31) g_bsum[b] = ss;       // block total
    }
    __syncthreads();
    if (idx < NN) g_start[idx] = (s - v) + wsum[w];
}

__global__ void k_scan2() {
    int lane = threadIdx.x;                   // 32 threads
    int i0 = 2 * lane, i1 = 2 * lane + 1;
    int a = (i0 < 49) ? g_bsum[i0] : 0;
    int b = (i1 < 49) ? g_bsum[i1] : 0;
    int pair = a + b;
    int s = pair;
#pragma unroll
    for (int o = 1; o < 32; o <<= 1) {
        int u = __shfl_up_sync(0xFFFFFFFFu, s, o);
        if (lane >= o) s += u;
    }
    if (i0 < 64) g_boff[i0] = s - pair;
    if (i1 < 64) g_boff[i1] = s - b;
}

__global__ void k_scan3() {
    int idx = blockIdx.x * 256 + threadIdx.x;
    if (idx < NN) g_start[idx] += g_boff[idx >> 10];
    if (idx == NN) g_start[NN] = ET;
}

__global__ void k_scatter(const int* __restrict__ ei) {
    int e = blockIdx.x * 256 + threadIdx.x;
    if (e >= ET) return;
    int s = (e < EE) ? ei[e] : e - EE;
    int d = (e < EE) ? ei[EE + e] : e - EE;
    int p = g_start[d] + atomicAdd(&g_cursor[d], 1);
    g_csr_src[p] = s;
}

// ---------------- fp16 conversion of X, W1l, W1r -----------------------------
#define NX (NN * 128 / 8)          // 800000
#define NW (128 * 256 / 8)         // 4096
__global__ void k_cvt(const float* __restrict__ X,
                      const float* __restrict__ Wl,
                      const float* __restrict__ Wr) {
    int i = blockIdx.x * 256 + threadIdx.x;
    const float* src;
    __half* dst;
    int j;
    if (i < NX)              { src = X;  dst = g_xh;  j = i; }
    else if (i < NX + NW)    { src = Wl; dst = g_wlh; j = i - NX; }
    else if (i < NX + 2*NW)  { src = Wr; dst = g_wrh; j = i - NX - NW; }
    else return;
    float4 a = *(const float4*)(src + (size_t)j * 8);
    float4 b = *(const float4*)(src + (size_t)j * 8 + 4);
    uint4 o;
    *(__half2*)&o.x = __floats2half2_rn(a.x, a.y);
    *(__half2*)&o.y = __floats2half2_rn(a.z, a.w);
    *(__half2*)&o.z = __floats2half2_rn(b.x, b.y);
    *(__half2*)&o.w = __floats2half2_rn(b.z, b.w);
    *(uint4*)(dst + (size_t)j * 8) = o;
}

// ---------------- fp16 mma helper ---------------------------------------------
__device__ __forceinline__ void mma_f16(float c[4], const uint32_t a[4], const uint32_t b[2]) {
    asm volatile(
        "mma.sync.aligned.m16n8k16.row.col.f32.f16.f16.f32 "
        "{%0,%1,%2,%3},{%4,%5,%6,%7},{%8,%9},{%0,%1,%2,%3};"
        : "+f"(c[0]), "+f"(c[1]), "+f"(c[2]), "+f"(c[3])
        : "r"(a[0]), "r"(a[1]), "r"(a[2]), "r"(a[3]), "r"(b[0]), "r"(b[1]));
}

__device__ __forceinline__ void cpa16(void* smem_ptr, const void* gmem_ptr, int src_sz) {
    uint32_t saddr = (uint32_t)__cvta_generic_to_shared(smem_ptr);
    asm volatile("cp.async.cg.shared.global [%0], [%1], 16, %2;"
                 :: "r"(saddr), "l"(gmem_ptr), "r"(src_sz));
}

// ---------------- GEMM1 (fp16 TC, cp.async 2-stage, BK=32) -------------------
#define LDAH 40
#define LDBH 136
__global__ void __launch_bounds__(256, 2) k_gemm1() {
    __shared__ __half As[2][128 * LDAH];   // [m][k]
    __shared__ __half Bs[2][32 * LDBH];    // [k][n]
    const int bm = blockIdx.y * 128;
    const int bn = blockIdx.x * 128;
    const __half* Bsrc = (bn < 256) ? g_wlh : g_wrh;
    const int bnl = bn & 255;

    const int tid = threadIdx.x;
    const int wid = tid >> 5, lane = tid & 31;
    const int wm = wid >> 2, wn = wid & 3;
    const int g = lane >> 2, tg = lane & 3;

    float acc[4][4][4];
#pragma unroll
    for (int mt = 0; mt < 4; mt++)
#pragma unroll
        for (int nt = 0; nt < 4; nt++)
#pragma unroll
            for (int r = 0; r < 4; r++) acc[mt][nt][r] = 0.f;

    const int am0 = tid >> 2,          akc = (tid & 3) * 8;
    const int am1 = (tid + 256) >> 2;
    const int bk0 = tid >> 4,          bnf = (tid & 15) * 8;
    const int bk1 = (tid + 256) >> 4;

#define STAGE(slab, buf)                                                          \
    {                                                                             \
        int k0 = (slab) * 32;                                                     \
        cpa16(&As[buf][am0 * LDAH + akc],                                         \
              g_xh + (size_t)(bm + am0) * 128 + k0 + akc,                         \
              (bm + am0 < NN) ? 16 : 0);                                          \
        cpa16(&As[buf][am1 * LDAH + akc],                                         \
              g_xh + (size_t)(bm + am1) * 128 + k0 + akc,                         \
              (bm + am1 < NN) ? 16 : 0);                                          \
        cpa16(&Bs[buf][bk0 * LDBH + bnf],                                         \
              Bsrc + (size_t)(k0 + bk0) * 256 + bnl + bnf, 16);                   \
        cpa16(&Bs[buf][bk1 * LDBH + bnf],                                         \
              Bsrc + (size_t)(k0 + bk1) * 256 + bnl + bnf, 16);                   \
        asm volatile("cp.async.commit_group;");                                   \
    }

    STAGE(0, 0);

#pragma unroll
    for (int i = 0; i < 4; i++) {
        const int cur = i & 1;
        if (i < 3) STAGE(i + 1, cur ^ 1);
        if (i < 3) asm volatile("cp.async.wait_group 1;");
        else       asm volatile("cp.async.wait_group 0;");
        __syncthreads();

        const uint16_t* BsU = (const uint16_t*)Bs[cur];
#pragma unroll
        for (int ks = 0; ks < 2; ks++) {
            int kb = ks * 16;
            uint32_t a[4][4], b[4][2];
#pragma unroll
            for (int mt = 0; mt < 4; mt++) {
                int rb = wm * 64 + mt * 16 + g;
                a[mt][0] = *(const uint32_t*)(As[cur] + rb * LDAH + kb + 2 * tg);
                a[mt][1] = *(const uint32_t*)(As[cur] + (rb + 8) * LDAH + kb + 2 * tg);
                a[mt][2] = *(const uint32_t*)(As[cur] + rb * LDAH + kb + 2 * tg + 8);
                a[mt][3] = *(const uint32_t*)(As[cur] + (rb + 8) * LDAH + kb + 2 * tg + 8);
            }
#pragma unroll
            for (int nt = 0; nt < 4; nt++) {
                int cb = wn * 32 + nt * 8 + g;
                uint32_t lo0 = BsU[(kb + 2 * tg) * LDBH + cb];
                uint32_t hi0 = BsU[(kb + 2 * tg + 1) * LDBH + cb];
                uint32_t lo1 = BsU[(kb + 2 * tg + 8) * LDBH + cb];
                uint32_t hi1 = BsU[(kb + 2 * tg + 9) * LDBH + cb];
                b[nt][0] = lo0 | (hi0 << 16);
                b[nt][1] = lo1 | (hi1 << 16);
            }
#pragma unroll
            for (int mt = 0; mt < 4; mt++)
#pragma unroll
                for (int nt = 0; nt < 4; nt++)
                    mma_f16(acc[mt][nt], a[mt], b[nt]);
        }
        __syncthreads();
    }

    __half2* dst = (__half2*)((bn < 256) ? g_xl1h : g_xr1h);
#pragma unroll
    for (int mt = 0; mt < 4; mt++) {
        int row0 = bm + wm * 64 + mt * 16 + g;
#pragma unroll
        for (int nt = 0; nt < 4; nt++) {
            int col = bnl + wn * 32 + nt * 8 + 2 * tg;   // even
            if (row0 < NN)
                dst[((size_t)row0 * 256 + col) >> 1] =
                    __floats2half2_rn(acc[mt][nt][0], acc[mt][nt][1]);
            if (row0 + 8 < NN)
                dst[((size_t)(row0 + 8) * 256 + col) >> 1] =
                    __floats2half2_rn(acc[mt][nt][2], acc[mt][nt][3]);
        }
    }
}

// ---- layer-1 fused: score + online softmax + aggregate + b1 + ELU -----------
// warp per node; lane = h*4+q owns 8 contiguous (fp16) floats of head h.
// 2-edge unrolled main loop for ILP (independent load/score/shuffle chains).
__global__ void k_fused1(const float* __restrict__ att1, const float* __restrict__ b1) {
    int t = threadIdx.x;
    int node = blockIdx.x * 8 + (t >> 5);
    if (node >= NN) return;
    int lane = t & 31, h = lane >> 2, q = lane & 3;
    int base = h * 32 + q * 8;
    int p0 = g_start[node], p1 = g_start[node + 1];

    float4 at0 = *(const float4*)(att1 + base);
    float4 at1 = *(const float4*)(att1 + base + 4);

    uint4 rr = *(const uint4*)(g_xr1h + (size_t)node * 256 + base);
    float2 xrA = __half22float2(*(__half2*)&rr.x);
    float2 xrB = __half22float2(*(__half2*)&rr.y);
    float2 xrC = __half22float2(*(__half2*)&rr.z);
    float2 xrD = __half22float2(*(__half2*)&rr.w);

    float m = -1e30f, den = 0.f;
    float acc[8];
#pragma unroll
    for (int i = 0; i < 8; i++) acc[i] = 0.f;

#define SCORE8(lA, lB, lC, lD, sc)                                              \
    {                                                                           \
        float v;                                                                \
        v = lA.x + xrA.x; v = v > 0.f ? v : 0.2f * v; sc  = at0.x * v;          \
        v = lA.y + xrA.y; v = v > 0.f ? v : 0.2f * v; sc += at0.y * v;          \
        v = lB.x + xrB.x; v = v > 0.f ? v : 0.2f * v; sc += at0.z * v;          \
        v = lB.y + xrB.y; v = v > 0.f ? v : 0.2f * v; sc += at0.w * v;          \
        v = lC.x + xrC.x; v = v > 0.f ? v : 0.2f * v; sc += at1.x * v;          \
        v = lC.y + xrC.y; v = v > 0.f ? v : 0.2f * v; sc += at1.y * v;          \
        v = lD.x + xrD.x; v = v > 0.f ? v : 0.2f * v; sc += at1.z * v;          \
        v = lD.y + xrD.y; v = v > 0.f ? v : 0.2f * v; sc += at1.w * v;          \
    }

#define UPDATE8(lA, lB, lC, lD, sc)                                             \
    if (sc <= m) {                                                              \
        float w = __expf(sc - m);                                               \
        den += w;                                                               \
        acc[0] += w * lA.x; acc[1] += w * lA.y; acc[2] += w * lB.x;             \
        acc[3] += w * lB.y; acc[4] += w * lC.x; acc[5] += w * lC.y;             \
        acc[6] += w * lD.x; acc[7] += w * lD.y;                                 \
    } else {                                                                    \
        float sfac = __expf(m - sc);                                            \
        den = den * sfac + 1.f;                                                 \
        acc[0] = acc[0] * sfac + lA.x; acc[1] = acc[1] * sfac + lA.y;           \
        acc[2] = acc[2] * sfac + lB.x; acc[3] = acc[3] * sfac + lB.y;           \
        acc[4] = acc[4] * sfac + lC.x; acc[5] = acc[5] * sfac + lC.y;           \
        acc[6] = acc[6] * sfac + lD.x; acc[7] = acc[7] * sfac + lD.y;           \
        m = sc;                                                                 \
    }

    int p = p0;
    for (; p + 2 <= p1; p += 2) {
        int s0 = g_csr_src[p];
        int s1 = g_csr_src[p + 1];
        uint4 r0 = *(const uint4*)(g_xl1h + (size_t)s0 * 256 + base);
        uint4 r1 = *(const uint4*)(g_xl1h + (size_t)s1 * 256 + base);
        float2 aA = __half22float2(*(__half2*)&r0.x);
        float2 aB = __half22float2(*(__half2*)&r0.y);
        float2 aC = __half22float2(*(__half2*)&r0.z);
        float2 aD = __half22float2(*(__half2*)&r0.w);
        float2 bA = __half22float2(*(__half2*)&r1.x);
        float2 bB = __half22float2(*(__half2*)&r1.y);
        float2 bC = __half22float2(*(__half2*)&r1.z);
        float2 bD = __half22float2(*(__half2*)&r1.w);

        float sc0, sc1;
        SCORE8(aA, aB, aC, aD, sc0);
        SCORE8(bA, bB, bC, bD, sc1);
        // interleaved butterflies: the two chains are independent
        sc0 += __shfl_xor_sync(0xFFFFFFFFu, sc0, 1);
        sc1 += __shfl_xor_sync(0xFFFFFFFFu, sc1, 1);
        sc0 += __shfl_xor_sync(0xFFFFFFFFu, sc0, 2);
        sc1 += __shfl_xor_sync(0xFFFFFFFFu, sc1, 2);

        UPDATE8(aA, aB, aC, aD, sc0);
        UPDATE8(bA, bB, bC, bD, sc1);
    }
    if (p < p1) {
        int s0 = g_csr_src[p];
        uint4 r0 = *(const uint4*)(g_xl1h + (size_t)s0 * 256 + base);
        float2 aA = __half22float2(*(__half2*)&r0.x);
        float2 aB = __half22float2(*(__half2*)&r0.y);
        float2 aC = __half22float2(*(__half2*)&r0.z);
        float2 aD = __half22float2(*(__half2*)&r0.w);
        float sc0;
        SCORE8(aA, aB, aC, aD, sc0);
        sc0 += __shfl_xor_sync(0xFFFFFFFFu, sc0, 1);
        sc0 += __shfl_xor_sync(0xFFFFFFFFu, sc0, 2);
        UPDATE8(aA, aB, aC, aD, sc0);
    }

    float inv = 1.f / (den + 1e-16f);
    float4 bb0 = *(const float4*)(b1 + base);
    float4 bb1 = *(const float4*)(b1 + base + 4);
    float o[8];
    o[0] = acc[0] * inv + bb0.x; o[1] = acc[1] * inv + bb0.y;
    o[2] = acc[2] * inv + bb0.z; o[3] = acc[3] * inv + bb0.w;
    o[4] = acc[4] * inv + bb1.x; o[5] = acc[5] * inv + bb1.y;
    o[6] = acc[6] * inv + bb1.z; o[7] = acc[7] * inv + bb1.w;
#pragma unroll
    for (int i = 0; i < 8; i++) o[i] = o[i] > 0.f ? o[i] : expm1f(o[i]);

    uint4 packed;
    *(__half2*)&packed.x = __floats2half2_rn(o[0], o[1]);
    *(__half2*)&packed.y = __floats2half2_rn(o[2], o[3]);
    *(__half2*)&packed.z = __floats2half2_rn(o[4], o[5]);
    *(__half2*)&packed.w = __floats2half2_rn(o[6], o[7]);
    *(uint4*)(g_h1 + (size_t)node * 256 + base) = packed;
}

// ---------------- GEMM2: h[NN,256](fp16) @ [W2l | W2r][256,32] ---------------
__global__ void k_gemm2(const float* __restrict__ Wl, const float* __restrict__ Wr) {
    __shared__ float ws[256 * 32];
    __shared__ float hs[16][256];
    int tid = threadIdx.x;
    for (int i = tid; i < 256 * 32; i += 256) {
        int k = i >> 5, c = i & 31;
        ws[i] = (c < 16) ? Wl[k * 16 + c] : Wr[k * 16 + c - 16];
    }
    int node0 = blockIdx.x * 16;
    const __half2* hp = (const __half2*)g_h1;
    for (int i = tid; i < 16 * 128; i += 256) {
        int m = i >> 7, kk = (i & 127) * 2;
        int node = node0 + m;
        float2 v = make_float2(0.f, 0.f);
        if (node < NN) v = __half22float2(hp[((size_t)node * 256 + kk) >> 1]);
        hs[m][kk] = v.x;
        hs[m][kk + 1] = v.y;
    }
    __syncthreads();
    int c = tid & 31;
#pragma unroll
    for (int half = 0; half < 2; half++) {
        int m = (tid >> 5) + half * 8;
        int node = node0 + m;
        if (node < NN) {
            float sacc = 0.f;
#pragma unroll 8
            for (int k = 0; k < 256; k++) sacc += hs[m][k] * ws[k * 32 + c];
            if (c < 16) g_xl2[node * 16 + c] = sacc;
            else        g_xr2[node * 16 + c - 16] = sacc;
        }
    }
}

// ------- layer-2 fused: 2 nodes per warp (16 lanes each), online softmax -----
__global__ void k_fused2(const float* __restrict__ att2, const float* __restrict__ b2,
                         float* __restrict__ dout) {
    int t = threadIdx.x;
    int lane = t & 31;
    int half = lane >> 4, c = lane & 15;
    int node = blockIdx.x * 16 + (t >> 5) * 2 + half;   // NN % 16 == 0 -> always valid
    int p0 = g_start[node], p1 = g_start[node + 1];
    int deg = p1 - p0;
    int dego = __shfl_xor_sync(0xFFFFFFFFu, deg, 16);
    int nit = deg > dego ? deg : dego;

    float xr = g_xr2[node * 16 + c];
    float at = att2[c];
    float m = -1e30f, den = 0.f, acc = 0.f;

    for (int i = 0; i < nit; i++) {
        bool val = i < deg;
        int p = val ? (p0 + i) : p0;
        int s = g_csr_src[p];
        float xl = g_xl2[s * 16 + c];
        float v = xl + xr;
        v = v > 0.f ? v : 0.2f * v;
        float sc = v * at;
        sc += __shfl_xor_sync(0xFFFFFFFFu, sc, 8);
        sc += __shfl_xor_sync(0xFFFFFFFFu, sc, 4);
        sc += __shfl_xor_sync(0xFFFFFFFFu, sc, 2);
        sc += __shfl_xor_sync(0xFFFFFFFFu, sc, 1);
        if (!val) sc = -1e38f;
        if (sc <= m) {
            float w = __expf(sc - m);
            den += w;
            acc += w * xl;
        } else {
            float sfac = __expf(m - sc);
            den = den * sfac + 1.f;
            acc = acc * sfac + xl;
            m = sc;
        }
    }
    float v = acc / (den + 1e-16f) + b2[c];
    dout[node * 16 + c] = v >= 0.f ? v : 0.01f * v;
}

// ---------------- launch ------------------------------------------------------
extern "C" void kernel_launch(void* const* d_in, const int* in_sizes, int n_in,
                              void* d_out, int out_size) {
    const float* x    = (const float*)d_in[0];
    const int*   ei   = (const int*)d_in[1];
    const float* W1l  = (const float*)d_in[2];
    const float* W1r  = (const float*)d_in[3];
    const float* att1 = (const float*)d_in[4];
    const float* b1   = (const float*)d_in[5];
    const float* W2l  = (const float*)d_in[6];
    const float* W2r  = (const float*)d_in[7];
    const float* att2 = (const float*)d_in[8];
    const float* b2   = (const float*)d_in[9];
    float* out = (float*)d_out;

    // one-time host-object creation (no device memory)
    static cudaStream_t s2 = nullptr;
    static cudaEvent_t evFork = nullptr, evJoin = nullptr;
    if (s2 == nullptr) {
        cudaStreamCreateWithFlags(&s2, cudaStreamNonBlocking);
        cudaEventCreateWithFlags(&evFork, cudaEventDisableTiming);
        cudaEventCreateWithFlags(&evJoin, cudaEventDisableTiming);
    }

    // fork: CSR chain on s2, cvt+gemm1 on main stream
    cudaEventRecord(evFork, 0);
    cudaStreamWaitEvent(s2, evFork, 0);

    k_init<<<(NN + 255) / 256, 256, 0, s2>>>();
    k_hist<<<(EE / 4 + 255) / 256, 256, 0, s2>>>(ei);
    k_scan1<<<49, 1024, 0, s2>>>();
    k_scan2<<<1, 32, 0, s2>>>();
    k_scan3<<<(NN + 256) / 256, 256, 0, s2>>>();
    k_scatter<<<(ET + 255) / 256, 256, 0, s2>>>(ei);
    cudaEventRecord(evJoin, s2);

    k_cvt<<<(NX + 2 * NW + 255) / 256, 256>>>(x, W1l, W1r);
    dim3 g1(4, (NN + 127) / 128);
    k_gemm1<<<g1, 256>>>();

    // join: fused1 needs both CSR and gemm1 results
    cudaStreamWaitEvent(0, evJoin, 0);

    k_fused1<<<(NN + 7) / 8, 256>>>(att1, b1);

    k_gemm2<<<(NN + 15) / 16, 256>>>(W2l, W2r);

    k_fused2<<<NN / 16, 256>>>(att2, b2, out);
}

// round 16
// speedup vs baseline: 2.1215x; 1.4584x over previous
#include <cuda_runtime.h>
#include <cuda_fp16.h>
#include <math.h>
#include <stdint.h>

#define NN 50000
#define EE 640000
#define ET 690000   // EE + NN self loops

// ---------------- scratch (device globals) ----------------------------------
__device__ __half g_xh[(size_t)NN * 128];      // X in fp16
__device__ __half g_wlh[128 * 256];            // W1l fp16
__device__ __half g_wrh[128 * 256];            // W1r fp16
__device__ __half g_w2h[256 * 32];             // [W2l|W2r] fp16, [k][c]
__device__ __half g_xl1h[(size_t)NN * 256];
__device__ __half g_xr1h[(size_t)NN * 256];
__device__ __half g_h1[(size_t)NN * 256];      // layer-1 output (post-ELU), fp16
__device__ float  g_xl2[NN * 16];
__device__ float  g_xr2[NN * 16];
__device__ int    g_deg[NN];
__device__ int    g_start[NN + 1];
__device__ int    g_cursor[NN];
__device__ int    g_csr_src[ET];
__device__ int    g_bsum[64];

// ---------------- CSR construction ------------------------------------------
__global__ void k_init() {
    int i = blockIdx.x * 256 + threadIdx.x;
    if (i < NN) { g_deg[i] = 1; g_cursor[i] = 0; }   // deg=1: self loop pre-counted
}

__global__ void k_hist(const int* __restrict__ ei) {
    int e = (blockIdx.x * 256 + threadIdx.x) * 4;
    if (e + 4 <= EE) {
        int4 d = *(const int4*)(ei + EE + e);
        atomicAdd(&g_deg[d.x], 1);
        atomicAdd(&g_deg[d.y], 1);
        atomicAdd(&g_deg[d.z], 1);
        atomicAdd(&g_deg[d.w], 1);
    }
}

// ---- 2-phase multi-block scan --------------------------------------------------
__global__ void k_scan1() {
    __shared__ int wsum[32];
    int b = blockIdx.x, t = threadIdx.x;
    int idx = b * 1024 + t;
    int v = (idx < NN) ? g_deg[idx] : 0;
    int lane = t & 31, w = t >> 5;
    int s = v;
#pragma unroll
    for (int o = 1; o < 32; o <<= 1) {
        int u = __shfl_up_sync(0xFFFFFFFFu, s, o);
        if (lane >= o) s += u;
    }
    if (lane == 31) wsum[w] = s;
    __syncthreads();
    if (w == 0) {
        int ws = wsum[lane];
        int ss = ws;
#pragma unroll
        for (int o = 1; o < 32; o <<= 1) {
            int u = __shfl_up_sync(0xFFFFFFFFu, ss, o);
            if (lane >= o) ss += u;
        }
        wsum[lane] = ss - ws;                 // exclusive warp offset
        if (lane == 31) g_bsum[b] = ss;       // block total
    }
    __syncthreads();
    if (idx < NN) g_start[idx] = (s - v) + wsum[w];
}

// phase 2 (merged): each block redundantly scans the 49 block totals, then adds
__global__ void k_scan3() {
    __shared__ int s_boff[64];
    int t = threadIdx.x;
    if (t < 32) {
        int i0 = 2 * t, i1 = 2 * t + 1;
        int a = (i0 < 49) ? g_bsum[i0] : 0;
        int b = (i1 < 49) ? g_bsum[i1] : 0;
        int pair = a + b;
        int s = pair;
#pragma unroll
        for (int o = 1; o < 32; o <<= 1) {
            int u = __shfl_up_sync(0xFFFFFFFFu, s, o);
            if (t >= o) s += u;
        }
        if (i0 < 64) s_boff[i0] = s - pair;
        if (i1 < 64) s_boff[i1] = s - b;
    }
    __syncthreads();
    int idx = blockIdx.x * 256 + t;
    if (idx < NN) g_start[idx] += s_boff[idx >> 10];
    if (idx == NN) g_start[NN] = ET;
}

__global__ void k_scatter(const int* __restrict__ ei) {
    int e = blockIdx.x * 256 + threadIdx.x;
    if (e >= ET) return;
    int s = (e < EE) ? ei[e] : e - EE;
    int d = (e < EE) ? ei[EE + e] : e - EE;
    int p = g_start[d] + atomicAdd(&g_cursor[d], 1);
    g_csr_src[p] = s;
}

// ---------------- fp16 conversion of X, W1l, W1r, W2 -------------------------
#define NX (NN * 128 / 8)          // 800000
#define NW (128 * 256 / 8)         // 4096
#define NW2 (256 * 32 / 8)         // 1024
__global__ void k_cvt(const float* __restrict__ X,
                      const float* __restrict__ Wl,
                      const float* __restrict__ Wr,
                      const float* __restrict__ W2l,
                      const float* __restrict__ W2r) {
    int i = blockIdx.x * 256 + threadIdx.x;
    const float* src;
    __half* dst;
    int j;
    if (i < NX)                  { src = X;  dst = g_xh;  j = i; }
    else if (i < NX + NW)        { src = Wl; dst = g_wlh; j = i - NX; }
    else if (i < NX + 2 * NW)    { src = Wr; dst = g_wrh; j = i - NX - NW; }
    else if (i < NX + 2 * NW + NW2) {
        j = i - NX - 2 * NW;
        int k = (j * 8) >> 5;
        int c0 = (j * 8) & 31;                 // 0, 8, 16, 24
        src = (c0 < 16) ? (W2l + k * 16 + c0) : (W2r + k * 16 + (c0 - 16));
        dst = g_w2h;
        float4 a = *(const float4*)(src);
        float4 b = *(const float4*)(src + 4);
        uint4 o;
        *(__half2*)&o.x = __floats2half2_rn(a.x, a.y);
        *(__half2*)&o.y = __floats2half2_rn(a.z, a.w);
        *(__half2*)&o.z = __floats2half2_rn(b.x, b.y);
        *(__half2*)&o.w = __floats2half2_rn(b.z, b.w);
        *(uint4*)(dst + (size_t)j * 8) = o;
        return;
    }
    else return;
    float4 a = *(const float4*)(src + (size_t)j * 8);
    float4 b = *(const float4*)(src + (size_t)j * 8 + 4);
    uint4 o;
    *(__half2*)&o.x = __floats2half2_rn(a.x, a.y);
    *(__half2*)&o.y = __floats2half2_rn(a.z, a.w);
    *(__half2*)&o.z = __floats2half2_rn(b.x, b.y);
    *(__half2*)&o.w = __floats2half2_rn(b.z, b.w);
    *(uint4*)(dst + (size_t)j * 8) = o;
}

// ---------------- fp16 mma helper ---------------------------------------------
__device__ __forceinline__ void mma_f16(float c[4], const uint32_t a[4], const uint32_t b[2]) {
    asm volatile(
        "mma.sync.aligned.m16n8k16.row.col.f32.f16.f16.f32 "
        "{%0,%1,%2,%3},{%4,%5,%6,%7},{%8,%9},{%0,%1,%2,%3};"
        : "+f"(c[0]), "+f"(c[1]), "+f"(c[2]), "+f"(c[3])
        : "r"(a[0]), "r"(a[1]), "r"(a[2]), "r"(a[3]), "r"(b[0]), "r"(b[1]));
}

__device__ __forceinline__ void cpa16(void* smem_ptr, const void* gmem_ptr, int src_sz) {
    uint32_t saddr = (uint32_t)__cvta_generic_to_shared(smem_ptr);
    asm volatile("cp.async.cg.shared.global [%0], [%1], 16, %2;"
                 :: "r"(saddr), "l"(gmem_ptr), "r"(src_sz));
}

// ---------------- GEMM1 (fp16 TC, cp.async 2-stage, BK=32) -------------------
#define LDAH 40
#define LDBH 136
__global__ void __launch_bounds__(256, 2) k_gemm1() {
    __shared__ __half As[2][128 * LDAH];   // [m][k]
    __shared__ __half Bs[2][32 * LDBH];    // [k][n]
    const int bm = blockIdx.y * 128;
    const int bn = blockIdx.x * 128;
    const __half* Bsrc = (bn < 256) ? g_wlh : g_wrh;
    const int bnl = bn & 255;

    const int tid = threadIdx.x;
    const int wid = tid >> 5, lane = tid & 31;
    const int wm = wid >> 2, wn = wid & 3;
    const int g = lane >> 2, tg = lane & 3;

    float acc[4][4][4];
#pragma unroll
    for (int mt = 0; mt < 4; mt++)
#pragma unroll
        for (int nt = 0; nt < 4; nt++)
#pragma unroll
            for (int r = 0; r < 4; r++) acc[mt][nt][r] = 0.f;

    const int am0 = tid >> 2,          akc = (tid & 3) * 8;
    const int am1 = (tid + 256) >> 2;
    const int bk0 = tid >> 4,          bnf = (tid & 15) * 8;
    const int bk1 = (tid + 256) >> 4;

#define STAGE(slab, buf)                                                          \
    {                                                                             \
        int k0 = (slab) * 32;                                                     \
        cpa16(&As[buf][am0 * LDAH + akc],                                         \
              g_xh + (size_t)(bm + am0) * 128 + k0 + akc,                         \
              (bm + am0 < NN) ? 16 : 0);                                          \
        cpa16(&As[buf][am1 * LDAH + akc],                                         \
              g_xh + (size_t)(bm + am1) * 128 + k0 + akc,                         \
              (bm + am1 < NN) ? 16 : 0);                                          \
        cpa16(&Bs[buf][bk0 * LDBH + bnf],                                         \
              Bsrc + (size_t)(k0 + bk0) * 256 + bnl + bnf, 16);                   \
        cpa16(&Bs[buf][bk1 * LDBH + bnf],                                         \
              Bsrc + (size_t)(k0 + bk1) * 256 + bnl + bnf, 16);                   \
        asm volatile("cp.async.commit_group;");                                   \
    }

    STAGE(0, 0);

#pragma unroll
    for (int i = 0; i < 4; i++) {
        const int cur = i & 1;
        if (i < 3) STAGE(i + 1, cur ^ 1);
        if (i < 3) asm volatile("cp.async.wait_group 1;");
        else       asm volatile("cp.async.wait_group 0;");
        __syncthreads();

        const uint16_t* BsU = (const uint16_t*)Bs[cur];
#pragma unroll
        for (int ks = 0; ks < 2; ks++) {
            int kb = ks * 16;
            uint32_t a[4][4], b[4][2];
#pragma unroll
            for (int mt = 0; mt < 4; mt++) {
                int rb = wm * 64 + mt * 16 + g;
                a[mt][0] = *(const uint32_t*)(As[cur] + rb * LDAH + kb + 2 * tg);
                a[mt][1] = *(const uint32_t*)(As[cur] + (rb + 8) * LDAH + kb + 2 * tg);
                a[mt][2] = *(const uint32_t*)(As[cur] + rb * LDAH + kb + 2 * tg + 8);
                a[mt][3] = *(const uint32_t*)(As[cur] + (rb + 8) * LDAH + kb + 2 * tg + 8);
            }
#pragma unroll
            for (int nt = 0; nt < 4; nt++) {
                int cb = wn * 32 + nt * 8 + g;
                uint32_t lo0 = BsU[(kb + 2 * tg) * LDBH + cb];
                uint32_t hi0 = BsU[(kb + 2 * tg + 1) * LDBH + cb];
                uint32_t lo1 = BsU[(kb + 2 * tg + 8) * LDBH + cb];
                uint32_t hi1 = BsU[(kb + 2 * tg + 9) * LDBH + cb];
                b[nt][0] = lo0 | (hi0 << 16);
                b[nt][1] = lo1 | (hi1 << 16);
            }
#pragma unroll
            for (int mt = 0; mt < 4; mt++)
#pragma unroll
                for (int nt = 0; nt < 4; nt++)
                    mma_f16(acc[mt][nt], a[mt], b[nt]);
        }
        __syncthreads();
    }

    __half2* dst = (__half2*)((bn < 256) ? g_xl1h : g_xr1h);
#pragma unroll
    for (int mt = 0; mt < 4; mt++) {
        int row0 = bm + wm * 64 + mt * 16 + g;
#pragma unroll
        for (int nt = 0; nt < 4; nt++) {
            int col = bnl + wn * 32 + nt * 8 + 2 * tg;   // even
            if (row0 < NN)
                dst[((size_t)row0 * 256 + col) >> 1] =
                    __floats2half2_rn(acc[mt][nt][0], acc[mt][nt][1]);
            if (row0 + 8 < NN)
                dst[((size_t)(row0 + 8) * 256 + col) >> 1] =
                    __floats2half2_rn(acc[mt][nt][2], acc[mt][nt][3]);
        }
    }
}

// ---- layer-1 fused: score + online softmax + aggregate + b1 + ELU -----------
__global__ void k_fused1(const float* __restrict__ att1, const float* __restrict__ b1) {
    int t = threadIdx.x;
    int node = blockIdx.x * 8 + (t >> 5);
    if (node >= NN) return;
    int lane = t & 31, h = lane >> 2, q = lane & 3;
    int base = h * 32 + q * 8;
    int p0 = g_start[node], p1 = g_start[node + 1];

    float4 at0 = *(const float4*)(att1 + base);
    float4 at1 = *(const float4*)(att1 + base + 4);

    uint4 rr = *(const uint4*)(g_xr1h + (size_t)node * 256 + base);
    float2 xrA = __half22float2(*(__half2*)&rr.x);
    float2 xrB = __half22float2(*(__half2*)&rr.y);
    float2 xrC = __half22float2(*(__half2*)&rr.z);
    float2 xrD = __half22float2(*(__half2*)&rr.w);

    float m = -1e30f, den = 0.f;
    float acc[8];
#pragma unroll
    for (int i = 0; i < 8; i++) acc[i] = 0.f;

#define SCORE8(lA, lB, lC, lD, sc)                                              \
    {                                                                           \
        float v;                                                                \
        v = lA.x + xrA.x; v = v > 0.f ? v : 0.2f * v; sc  = at0.x * v;          \
        v = lA.y + xrA.y; v = v > 0.f ? v : 0.2f * v; sc += at0.y * v;          \
        v = lB.x + xrB.x; v = v > 0.f ? v : 0.2f * v; sc += at0.z * v;          \
        v = lB.y + xrB.y; v = v > 0.f ? v : 0.2f * v; sc += at0.w * v;          \
        v = lC.x + xrC.x; v = v > 0.f ? v : 0.2f * v; sc += at1.x * v;          \
        v = lC.y + xrC.y; v = v > 0.f ? v : 0.2f * v; sc += at1.y * v;          \
        v = lD.x + xrD.x; v = v > 0.f ? v : 0.2f * v; sc += at1.z * v;          \
        v = lD.y + xrD.y; v = v > 0.f ? v : 0.2f * v; sc += at1.w * v;          \
    }

#define UPDATE8(lA, lB, lC, lD, sc)                                             \
    if (sc <= m) {                                                              \
        float w = __expf(sc - m);                                               \
        den += w;                                                               \
        acc[0] += w * lA.x; acc[1] += w * lA.y; acc[2] += w * lB.x;             \
        acc[3] += w * lB.y; acc[4] += w * lC.x; acc[5] += w * lC.y;             \
        acc[6] += w * lD.x; acc[7] += w * lD.y;                                 \
    } else {                                                                    \
        float sfac = __expf(m - sc);                                            \
        den = den * sfac + 1.f;                                                 \
        acc[0] = acc[0] * sfac + lA.x; acc[1] = acc[1] * sfac + lA.y;           \
        acc[2] = acc[2] * sfac + lB.x; acc[3] = acc[3] * sfac + lB.y;           \
        acc[4] = acc[4] * sfac + lC.x; acc[5] = acc[5] * sfac + lC.y;           \
        acc[6] = acc[6] * sfac + lD.x; acc[7] = acc[7] * sfac + lD.y;           \
        m = sc;                                                                 \
    }

    int p = p0;
    for (; p + 2 <= p1; p += 2) {
        int s0 = g_csr_src[p];
        int s1 = g_csr_src[p + 1];
        uint4 r0 = *(const uint4*)(g_xl1h + (size_t)s0 * 256 + base);
        uint4 r1 = *(const uint4*)(g_xl1h + (size_t)s1 * 256 + base);
        float2 aA = __half22float2(*(__half2*)&r0.x);
        float2 aB = __half22float2(*(__half2*)&r0.y);
        float2 aC = __half22float2(*(__half2*)&r0.z);
        float2 aD = __half22float2(*(__half2*)&r0.w);
        float2 bA = __half22float2(*(__half2*)&r1.x);
        float2 bB = __half22float2(*(__half2*)&r1.y);
        float2 bC = __half22float2(*(__half2*)&r1.z);
        float2 bD = __half22float2(*(__half2*)&r1.w);

        float sc0, sc1;
        SCORE8(aA, aB, aC, aD, sc0);
        SCORE8(bA, bB, bC, bD, sc1);
        sc0 += __shfl_xor_sync(0xFFFFFFFFu, sc0, 1);
        sc1 += __shfl_xor_sync(0xFFFFFFFFu, sc1, 1);
        sc0 += __shfl_xor_sync(0xFFFFFFFFu, sc0, 2);
        sc1 += __shfl_xor_sync(0xFFFFFFFFu, sc1, 2);

        UPDATE8(aA, aB, aC, aD, sc0);
        UPDATE8(bA, bB, bC, bD, sc1);
    }
    if (p < p1) {
        int s0 = g_csr_src[p];
        uint4 r0 = *(const uint4*)(g_xl1h + (size_t)s0 * 256 + base);
        float2 aA = __half22float2(*(__half2*)&r0.x);
        float2 aB = __half22float2(*(__half2*)&r0.y);
        float2 aC = __half22float2(*(__half2*)&r0.z);
        float2 aD = __half22float2(*(__half2*)&r0.w);
        float sc0;
        SCORE8(aA, aB, aC, aD, sc0);
        sc0 += __shfl_xor_sync(0xFFFFFFFFu, sc0, 1);
        sc0 += __shfl_xor_sync(0xFFFFFFFFu, sc0, 2);
        UPDATE8(aA, aB, aC, aD, sc0);
    }

    float inv = 1.f / (den + 1e-16f);
    float4 bb0 = *(const float4*)(b1 + base);
    float4 bb1 = *(const float4*)(b1 + base + 4);
    float o[8];
    o[0] = acc[0] * inv + bb0.x; o[1] = acc[1] * inv + bb0.y;
    o[2] = acc[2] * inv + bb0.z; o[3] = acc[3] * inv + bb0.w;
    o[4] = acc[4] * inv + bb1.x; o[5] = acc[5] * inv + bb1.y;
    o[6] = acc[6] * inv + bb1.z; o[7] = acc[7] * inv + bb1.w;
#pragma unroll
    for (int i = 0; i < 8; i++) o[i] = o[i] > 0.f ? o[i] : expm1f(o[i]);

    uint4 packed;
    *(__half2*)&packed.x = __floats2half2_rn(o[0], o[1]);
    *(__half2*)&packed.y = __floats2half2_rn(o[2], o[3]);
    *(__half2*)&packed.z = __floats2half2_rn(o[4], o[5]);
    *(__half2*)&packed.w = __floats2half2_rn(o[6], o[7]);
    *(uint4*)(g_h1 + (size_t)node * 256 + base) = packed;
}

// ---------------- GEMM2 (fp16 TC): h[NN,256] @ W2[256,32] --------------------
// 128-node tile, 8 warps (4m x 2n), warp tile 32x16, BK=64.
#define LDA2 72
#define LDB2 40
__global__ void __launch_bounds__(256) k_gemm2() {
    __shared__ __half As[128 * LDA2];   // [m][k]
    __shared__ __half Bs[64 * LDB2];    // [k][c]
    const int node0 = blockIdx.x * 128;
    const int tid = threadIdx.x;
    const int wid = tid >> 5, lane = tid & 31;
    const int wm = wid >> 1, wn = wid & 1;
    const int g = lane >> 2, tg = lane & 3;

    float acc[2][2][4];
#pragma unroll
    for (int mt = 0; mt < 2; mt++)
#pragma unroll
        for (int nt = 0; nt < 2; nt++)
#pragma unroll
            for (int r = 0; r < 4; r++) acc[mt][nt][r] = 0.f;

    for (int k0 = 0; k0 < 256; k0 += 64) {
#pragma unroll
        for (int it = 0; it < 4; it++) {
            int idx = tid + it * 256;
            int mm = idx >> 3, kc = (idx & 7) * 8;
            int node = node0 + mm;
            uint4 v = make_uint4(0u, 0u, 0u, 0u);
            if (node < NN) v = *(const uint4*)(g_h1 + (size_t)node * 256 + k0 + kc);
            *(uint4*)(As + mm * LDA2 + kc) = v;
        }
        {
            int k = tid >> 2, c = (tid & 3) * 8;
            *(uint4*)(Bs + k * LDB2 + c) = *(const uint4*)(g_w2h + (k0 + k) * 32 + c);
        }
        __syncthreads();

        const uint16_t* BsU = (const uint16_t*)Bs;
#pragma unroll
        for (int ks = 0; ks < 4; ks++) {
            int kb = ks * 16;
            uint32_t a[2][4], b[2][2];
#pragma unroll
            for (int mt = 0; mt < 2; mt++) {
                int rb = wm * 32 + mt * 16 + g;
                a[mt][0] = *(const uint32_t*)(As + rb * LDA2 + kb + 2 * tg);
                a[mt][1] = *(const uint32_t*)(As + (rb + 8) * LDA2 + kb + 2 * tg);
                a[mt][2] = *(const uint32_t*)(As + rb * LDA2 + kb + 2 * tg + 8);
                a[mt][3] = *(const uint32_t*)(As + (rb + 8) * LDA2 + kb + 2 * tg + 8);
            }
#pragma unroll
            for (int nt = 0; nt < 2; nt++) {
                int cb = wn * 16 + nt * 8 + g;
                uint32_t lo0 = BsU[(kb + 2 * tg) * LDB2 + cb];
                uint32_t hi0 = BsU[(kb + 2 * tg + 1) * LDB2 + cb];
                uint32_t lo1 = BsU[(kb + 2 * tg + 8) * LDB2 + cb];
                uint32_t hi1 = BsU[(kb + 2 * tg + 9) * LDB2 + cb];
                b[nt][0] = lo0 | (hi0 << 16);
                b[nt][1] = lo1 | (hi1 << 16);
            }
#pragma unroll
            for (int mt = 0; mt < 2; mt++)
#pragma unroll
                for (int nt = 0; nt < 2; nt++)
                    mma_f16(acc[mt][nt], a[mt], b[nt]);
        }
        __syncthreads();
    }

#pragma unroll
    for (int mt = 0; mt < 2; mt++) {
        int row0 = node0 + wm * 32 + mt * 16 + g;
#pragma unroll
        for (int nt = 0; nt < 2; nt++) {
            int col = wn * 16 + nt * 8 + 2 * tg;
            float* dstb = (col < 16) ? g_xl2 : g_xr2;
            int cc = col & 15;
            if (row0 < NN)
                *(float2*)(dstb + row0 * 16 + cc) = make_float2(acc[mt][nt][0], acc[mt][nt][1]);
            if (row0 + 8 < NN)
                *(float2*)(dstb + (row0 + 8) * 16 + cc) = make_float2(acc[mt][nt][2], acc[mt][nt][3]);
        }
    }
}

// ------- layer-2 fused: 2 nodes per warp (16 lanes each), online softmax -----
__global__ void k_fused2(const float* __restrict__ att2, const float* __restrict__ b2,
                         float* __restrict__ dout) {
    int t = threadIdx.x;
    int lane = t & 31;
    int half = lane >> 4, c = lane & 15;
    int node = blockIdx.x * 16 + (t >> 5) * 2 + half;   // NN % 16 == 0 -> always valid
    int p0 = g_start[node], p1 = g_start[node + 1];
    int deg = p1 - p0;
    int dego = __shfl_xor_sync(0xFFFFFFFFu, deg, 16);
    int nit = deg > dego ? deg : dego;

    float xr = g_xr2[node * 16 + c];
    float at = att2[c];
    float m = -1e30f, den = 0.f, acc = 0.f;

    for (int i = 0; i < nit; i++) {
        bool val = i < deg;
        int p = val ? (p0 + i) : p0;
        int s = g_csr_src[p];
        float xl = g_xl2[s * 16 + c];
        float v = xl + xr;
        v = v > 0.f ? v : 0.2f * v;
        float sc = v * at;
        sc += __shfl_xor_sync(0xFFFFFFFFu, sc, 8);
        sc += __shfl_xor_sync(0xFFFFFFFFu, sc, 4);
        sc += __shfl_xor_sync(0xFFFFFFFFu, sc, 2);
        sc += __shfl_xor_sync(0xFFFFFFFFu, sc, 1);
        if (!val) sc = -1e38f;
        if (sc <= m) {
            float w = __expf(sc - m);
            den += w;
            acc += w * xl;
        } else {
            float sfac = __expf(m - sc);
            den = den * sfac + 1.f;
            acc = acc * sfac + xl;
            m = sc;
        }
    }
    float v = acc / (den + 1e-16f) + b2[c];
    dout[node * 16 + c] = v >= 0.f ? v : 0.01f * v;
}

// ---------------- launch ------------------------------------------------------
extern "C" void kernel_launch(void* const* d_in, const int* in_sizes, int n_in,
                              void* d_out, int out_size) {
    const float* x    = (const float*)d_in[0];
    const int*   ei   = (const int*)d_in[1];
    const float* W1l  = (const float*)d_in[2];
    const float* W1r  = (const float*)d_in[3];
    const float* att1 = (const float*)d_in[4];
    const float* b1   = (const float*)d_in[5];
    const float* W2l  = (const float*)d_in[6];
    const float* W2r  = (const float*)d_in[7];
    const float* att2 = (const float*)d_in[8];
    const float* b2   = (const float*)d_in[9];
    float* out = (float*)d_out;

    // one-time host-object creation (no device memory)
    static cudaStream_t s2 = nullptr;
    static cudaEvent_t evFork = nullptr, evJoin = nullptr;
    if (s2 == nullptr) {
        cudaStreamCreateWithFlags(&s2, cudaStreamNonBlocking);
        cudaEventCreateWithFlags(&evFork, cudaEventDisableTiming);
        cudaEventCreateWithFlags(&evJoin, cudaEventDisableTiming);
    }

    // fork: CSR chain on s2, cvt+gemm1 on main stream
    cudaEventRecord(evFork, 0);
    cudaStreamWaitEvent(s2, evFork, 0);

    k_init<<<(NN + 255) / 256, 256, 0, s2>>>();
    k_hist<<<(EE / 4 + 255) / 256, 256, 0, s2>>>(ei);
    k_scan1<<<49, 1024, 0, s2>>>();
    k_scan3<<<(NN + 256) / 256, 256, 0, s2>>>();
    k_scatter<<<(ET + 255) / 256, 256, 0, s2>>>(ei);
    cudaEventRecord(evJoin, s2);

    k_cvt<<<(NX + 2 * NW + NW2 + 255) / 256, 256>>>(x, W1l, W1r, W2l, W2r);
    dim3 g1(4, (NN + 127) / 128);
    k_gemm1<<<g1, 256>>>();

    // join: fused1 needs both CSR and gemm1 results
    cudaStreamWaitEvent(0, evJoin, 0);

    k_fused1<<<(NN + 7) / 8, 256>>>(att1, b1);

    k_gemm2<<<(NN + 127) / 128, 256>>>();

    k_fused2<<<NN / 16, 256>>>(att2, b2, out);
}